// round 13
// baseline (speedup 1.0000x reference)
#include <cuda_runtime.h>
#include <cuda_fp16.h>
#include <math.h>
#include <stdint.h>
#include <mma.h>

using namespace nvcuda;

#define BATCH   4
#define LQ      1024
#define TSEQ    2048
#define DMODEL  256
#define DTIME   16
#define DDIM    272
#define KPAD1   288
#define NLAYER  4
#define DINNER  544
#define DSTATE  16
#define DCONV   4
#define DTRANK  17
#define NDBL    (DTRANK + 2*DSTATE)   // 49
#define MROWS   (BATCH*TSEQ)          // 8192
#define NCHUNK  64
#define CHUNK   (TSEQ/NCHUNK)         // 32
#define XK      576
#define XKS     (XK+8)
#define NX      64

typedef __half h16;

__device__ float g_h   [MROWS*DDIM];
__device__ float g_res [MROWS*DDIM];
__device__ float g_xz  [MROWS*2*DINNER];
__device__ float g_dbl2[MROWS*NX];
__device__ float g_hend[BATCH*NCHUNK*DINNER*DSTATE];
__device__ float g_P   [BATCH*NCHUNK*DINNER*DSTATE];
__device__ float g_Hin [BATCH*NCHUNK*DINNER*DSTATE];
__device__ float g_A2  [NLAYER*DINNER*DSTATE];
__device__ h16 g_hn [MROWS*KPAD1];
__device__ h16 g_yg [MROWS*DINNER];
__device__ h16 g_w1_hi[NLAYER*2*DINNER*KPAD1];
__device__ h16 g_w1_lo[NLAYER*2*DINNER*KPAD1];
__device__ h16 g_w2_hi[NLAYER*DDIM*DINNER];
__device__ h16 g_w2_lo[NLAYER*DDIM*DINNER];
__device__ h16 g_wx_hi[NLAYER*64*XK];
__device__ h16 g_wx_lo[NLAYER*64*XK];

__device__ __forceinline__ float ex2(float x) {
    float y; asm("ex2.approx.ftz.f32 %0, %1;" : "=f"(y) : "f"(x)); return y;
}
__device__ __forceinline__ void split_h16(float v, h16& hi, h16& lo) {
    hi = __float2half_rn(v);
    lo = __float2half_rn(v - __half2float(hi));
}
__device__ __forceinline__ void cp16(uint32_t saddr, const void* g, int srcsz) {
    asm volatile("cp.async.ca.shared.global [%0], [%1], 16, %2;\n"
                 :: "r"(saddr), "l"(g), "r"(srcsz));
}
__device__ __forceinline__ void cp_commit() { asm volatile("cp.async.commit_group;\n"); }
template<int NN> __device__ __forceinline__ void cp_wait() {
    asm volatile("cp.async.wait_group %0;\n" :: "n"(NN));
}

// ---------------- embedding ----------------
__global__ void __launch_bounds__(DDIM) embed_kernel(
    const int* __restrict__ type_seq, const float* __restrict__ time_seq,
    const float* __restrict__ temp_seq, const float* __restrict__ emb)
{
    int row = blockIdx.x;
    int d = threadIdx.x;
    int b = row / TSEQ, t = row % TSEQ;
    float v;
    if (t < LQ) {
        if (d < DMODEL) {
            v = tanhf(emb[(size_t)type_seq[b*LQ + t]*DMODEL + d]);
        } else {
            int j = d - DMODEL;
            int i = j >> 1;
            float div = expf(-0.57564627324851142f * (float)(2*i));
            float arg = time_seq[b*LQ + t] * div;
            v = (j & 1) ? cosf(arg) : sinf(arg);
        }
    } else {
        v = (d < DMODEL) ? 0.f
                         : temp_seq[(size_t)(b*LQ + (t - LQ))*DTIME + (d - DMODEL)];
    }
    g_h[(size_t)row*DDIM + d] = v;
}

// ---------------- one-time prep ----------------
#define W1TOT (NLAYER*2*DINNER*KPAD1)
#define W2TOT (NLAYER*DDIM*DINNER)
#define WXTOT (NLAYER*64*XK)
#define A2TOT (NLAYER*DINNER*DSTATE)
__global__ void __launch_bounds__(256) prep_all(
    const float* __restrict__ in_w, const float* __restrict__ out_w,
    const float* __restrict__ xproj_w, const float* __restrict__ A_log)
{
    int idx = blockIdx.x*256 + threadIdx.x;
    if (idx < W1TOT) {
        const int per = 2*DINNER*KPAD1;
        int l = idx / per, rem = idx - l*per;
        int r = rem / KPAD1, c = rem - r*KPAD1;
        float v = (c < DDIM) ? in_w[((size_t)l*2*DINNER + r)*DDIM + c] : 0.f;
        split_h16(v, g_w1_hi[idx], g_w1_lo[idx]);
    } else if (idx < W1TOT + W2TOT) {
        int j = idx - W1TOT;
        split_h16(out_w[j], g_w2_hi[j], g_w2_lo[j]);
    } else if (idx < W1TOT + W2TOT + WXTOT) {
        int j = idx - W1TOT - W2TOT;
        const int per = 64*XK;
        int l = j / per, rem = j - l*per;
        int r = rem / XK, cc = rem - r*XK;
        float v = (r < NDBL && cc < DINNER)
                ? xproj_w[((size_t)l*NDBL + r)*DINNER + cc] : 0.f;
        split_h16(v, g_wx_hi[j], g_wx_lo[j]);
    } else if (idx < W1TOT + W2TOT + WXTOT + A2TOT) {
        int j = idx - W1TOT - W2TOT - WXTOT;
        g_A2[j] = -__expf(A_log[j]) * 1.4426950408889634f;
    }
}

// ---------------- residual add + layernorm -> fp16 hn ----------------
__global__ void __launch_bounds__(128) addnorm_kernel(
    const float* __restrict__ gamma, const float* __restrict__ beta, int addflag)
{
    int row = blockIdx.x;
    int tid = threadIdx.x;
    float v[3];
    float s = 0.f, s2 = 0.f;
#pragma unroll
    for (int j = 0; j < 3; j++) {
        int d = tid + j*128;
        float x = 0.f;
        if (d < DDIM) {
            x = g_h[(size_t)row*DDIM + d];
            if (addflag) x += g_res[(size_t)row*DDIM + d];
        }
        v[j] = x; s += x; s2 += x*x;
    }
#pragma unroll
    for (int o = 16; o > 0; o >>= 1) {
        s  += __shfl_down_sync(0xffffffffu, s,  o);
        s2 += __shfl_down_sync(0xffffffffu, s2, o);
    }
    __shared__ float ss[4], ss2[4];
    if ((tid & 31) == 0) { ss[tid >> 5] = s; ss2[tid >> 5] = s2; }
    __syncthreads();
    if (tid == 0) {
        float a  = ss[0]+ss[1]+ss[2]+ss[3];
        float a2 = ss2[0]+ss2[1]+ss2[2]+ss2[3];
        float mean = a * (1.f/DDIM);
        float var  = a2 * (1.f/DDIM) - mean*mean;
        ss[0] = mean;
        ss2[0] = rsqrtf(var + 1e-5f);
    }
    __syncthreads();
    float mean = ss[0], rstd = ss2[0];
#pragma unroll
    for (int j = 0; j < 3; j++) {
        int d = tid + j*128;
        if (d < DDIM) {
            g_res[(size_t)row*DDIM + d] = v[j];
            float hn = (v[j]-mean)*rstd*gamma[d] + beta[d];
            g_hn[(size_t)row*KPAD1 + d] = __float2half_rn(hn);
        } else if (d < KPAD1) {
            g_hn[(size_t)row*KPAD1 + d] = __float2half(0.f);
        }
    }
}

// ---------------- final add + layernorm ----------------
__global__ void __launch_bounds__(128) final_kernel(
    const float* __restrict__ gamma, const float* __restrict__ beta,
    float* __restrict__ out)
{
    int rowo = blockIdx.x;
    int tid = threadIdx.x;
    int b = rowo / LQ, t = rowo % LQ;
    int m = b*TSEQ + t;
    float v[3];
    float s = 0.f, s2 = 0.f;
#pragma unroll
    for (int j = 0; j < 3; j++) {
        int d = tid + j*128;
        float x = 0.f;
        if (d < DDIM) x = g_h[(size_t)m*DDIM + d] + g_res[(size_t)m*DDIM + d];
        v[j] = x; s += x; s2 += x*x;
    }
#pragma unroll
    for (int o = 16; o > 0; o >>= 1) {
        s  += __shfl_down_sync(0xffffffffu, s,  o);
        s2 += __shfl_down_sync(0xffffffffu, s2, o);
    }
    __shared__ float ss[4], ss2[4];
    if ((tid & 31) == 0) { ss[tid >> 5] = s; ss2[tid >> 5] = s2; }
    __syncthreads();
    if (tid == 0) {
        float a  = ss[0]+ss[1]+ss[2]+ss[3];
        float a2 = ss2[0]+ss2[1]+ss2[2]+ss2[3];
        float mean = a * (1.f/DDIM);
        float var  = a2 * (1.f/DDIM) - mean*mean;
        ss[0] = mean;
        ss2[0] = rsqrtf(var + 1e-5f);
    }
    __syncthreads();
    float mean = ss[0], rstd = ss2[0];
#pragma unroll
    for (int j = 0; j < 3; j++) {
        int d = tid + j*128;
        if (d < DDIM)
            out[(size_t)rowo*DDIM + d] = (v[j]-mean)*rstd*gamma[d] + beta[d];
    }
}

// ---------------- fp16 2-term GEMM, cp.async 2-stage + slab skip ----------------
#define SPAD 8
#define SROW (32+SPAD)
__global__ void __launch_bounds__(256, 2) gemm_h16(
    const h16* __restrict__ A,
    const h16* __restrict__ Whi, const h16* __restrict__ Wlo,
    float* __restrict__ C, int M, int N, int Kpad)
{
    extern __shared__ h16 sm[];
    int tid = threadIdx.x;
    int warp = tid >> 5;
    int wm = warp >> 2;
    int wn = warp & 3;
    int mb = blockIdx.y * 128;
    int nb = blockIdx.x * 128;
    bool wnvalid = (nb + wn*32) < N;

    int aIdx0 = tid*2, aIdx1 = tid*2 + 1;
    int r0 = aIdx0 >> 2, c0 = (aIdx0 & 3) * 8;
    int r1 = aIdx1 >> 2, c1 = (aIdx1 & 3) * 8;
    int wsz0 = ((nb + r0) < N) ? 16 : 0;
    int wsz1 = ((nb + r1) < N) ? 16 : 0;

    const h16* pA0 = A   + (size_t)(mb + r0)*Kpad + c0;
    const h16* pA1 = A   + (size_t)(mb + r1)*Kpad + c1;
    const h16* pW0 = Whi + (size_t)(nb + r0)*Kpad + c0;
    const h16* pW1 = Whi + (size_t)(nb + r1)*Kpad + c1;
    const h16* pV0 = Wlo + (size_t)(nb + r0)*Kpad + c0;
    const h16* pV1 = Wlo + (size_t)(nb + r1)*Kpad + c1;

    uint32_t sbase = (uint32_t)__cvta_generic_to_shared(sm);
    auto soff = [&](int stage, int arr, int row, int col) -> uint32_t {
        return (uint32_t)((((stage*3 + arr)*128) + row)*SROW + col);
    };
    uint32_t dA0 = soff(0,0,r0,c0), dA1 = soff(0,0,r1,c1);
    uint32_t dW0 = soff(0,1,r0,c0), dW1 = soff(0,1,r1,c1);
    uint32_t dV0 = soff(0,2,r0,c0), dV1 = soff(0,2,r1,c1);
    const uint32_t STG = 3*128*SROW;

    wmma::fragment<wmma::accumulator,16,16,16,float> acc[4][2];
#pragma unroll
    for (int i = 0; i < 4; i++)
#pragma unroll
        for (int j = 0; j < 2; j++) wmma::fill_fragment(acc[i][j], 0.f);

    int ktiles = Kpad >> 5;

    cp16(sbase + 2*dA0, pA0, 16); cp16(sbase + 2*dA1, pA1, 16);
    cp16(sbase + 2*dW0, pW0, wsz0); cp16(sbase + 2*dW1, pW1, wsz1);
    cp16(sbase + 2*dV0, pV0, wsz0); cp16(sbase + 2*dV1, pV1, wsz1);
    cp_commit();

    for (int kt = 0; kt < ktiles; kt++) {
        if (kt + 1 < ktiles) {
            int st = (kt+1) & 1;
            int go = (kt+1) * 32;
            uint32_t so = st * STG;
            cp16(sbase + 2*(dA0+so), pA0 + go, 16); cp16(sbase + 2*(dA1+so), pA1 + go, 16);
            cp16(sbase + 2*(dW0+so), pW0 + go, wsz0); cp16(sbase + 2*(dW1+so), pW1 + go, wsz1);
            cp16(sbase + 2*(dV0+so), pV0 + go, wsz0); cp16(sbase + 2*(dV1+so), pV1 + go, wsz1);
            cp_commit();
            cp_wait<1>();
        } else {
            cp_wait<0>();
        }
        __syncthreads();

        if (wnvalid) {
            const h16* bA   = sm + (size_t)(kt&1)*STG + 0*128*SROW;
            const h16* bWhi = sm + (size_t)(kt&1)*STG + 1*128*SROW;
            const h16* bWlo = sm + (size_t)(kt&1)*STG + 2*128*SROW;
#pragma unroll
            for (int ks = 0; ks < 32; ks += 16) {
                wmma::fragment<wmma::matrix_b,16,16,16,h16,wmma::col_major> bhi[2], blo[2];
#pragma unroll
                for (int j = 0; j < 2; j++) {
                    wmma::load_matrix_sync(bhi[j], bWhi + (wn*32 + j*16)*SROW + ks, SROW);
                    wmma::load_matrix_sync(blo[j], bWlo + (wn*32 + j*16)*SROW + ks, SROW);
                }
#pragma unroll
                for (int i = 0; i < 4; i++) {
                    wmma::fragment<wmma::matrix_a,16,16,16,h16,wmma::row_major> af;
                    wmma::load_matrix_sync(af, bA + (wm*64 + i*16)*SROW + ks, SROW);
#pragma unroll
                    for (int j = 0; j < 2; j++) {
                        wmma::mma_sync(acc[i][j], af, bhi[j], acc[i][j]);
                        wmma::mma_sync(acc[i][j], af, blo[j], acc[i][j]);
                    }
                }
            }
        }
        __syncthreads();
    }
    if (wnvalid) {
#pragma unroll
        for (int i = 0; i < 4; i++)
#pragma unroll
            for (int j = 0; j < 2; j++) {
                int n0 = nb + wn*32 + j*16;
                if (n0 < N)
                    wmma::store_matrix_sync(C + (size_t)(mb + wm*64 + i*16)*N + n0,
                                            acc[i][j], N, wmma::mem_row_major);
            }
    }
}
#define GEMM_SMEM (2*3*128*SROW*2)   // 61440 bytes

// ---------------- mega1: conv + x_proj (3-term fp16 tensor) + scan1 ----------------
// CHUNK=32: smem ~102KB -> 2 CTAs/SM, 256 blocks.
#define MG_AHI  0
#define MG_ALO  (CHUNK*XKS*2)
#define MG_WH   (2*CHUNK*XKS*2)
#define MG_WL   (MG_WH + 64*72*2)
#define MG_DBL  (MG_WL + 64*72*2)
#define MG_SMEM (MG_DBL + CHUNK*68*4)
__global__ void __launch_bounds__(DINNER) mega1(
    const float* __restrict__ conv_w, const float* __restrict__ conv_b,
    const float* __restrict__ dt_w, const float* __restrict__ dt_b,
    int layer)
{
    extern __shared__ __align__(16) char smx[];
    h16*  Ahi  = (h16*)(smx + MG_AHI);
    h16*  Alo  = (h16*)(smx + MG_ALO);
    h16*  Wh   = (h16*)(smx + MG_WH);
    h16*  Wl   = (h16*)(smx + MG_WL);
    float* sdbl = (float*)(smx + MG_DBL);

    int c = blockIdx.x, b = blockIdx.y;
    int tid = threadIdx.x;
    int d = tid;
    int warp = tid >> 5;
    int t0 = c*CHUNK;
    int m0 = b*TSEQ + t0;

    // ---- conv phase (MLP-batched loads) ----
    {
        const float* wp = conv_w + (size_t)(layer*DINNER + d)*DCONV;
        float w0 = wp[0], w1 = wp[1], w2 = wp[2], w3 = wp[3];
        float bias = conv_b[layer*DINNER + d];
        size_t base = (size_t)(b*TSEQ)*(2*DINNER) + d;
        float x0 = (t0-3 >= 0) ? g_xz[base + (size_t)(t0-3)*(2*DINNER)] : 0.f;
        float x1 = (t0-2 >= 0) ? g_xz[base + (size_t)(t0-2)*(2*DINNER)] : 0.f;
        float x2 = (t0-1 >= 0) ? g_xz[base + (size_t)(t0-1)*(2*DINNER)] : 0.f;
        for (int i0 = 0; i0 < CHUNK; i0 += 8) {
            float xv[8];
#pragma unroll
            for (int j = 0; j < 8; j++)
                xv[j] = g_xz[base + (size_t)(t0+i0+j)*(2*DINNER)];
#pragma unroll
            for (int j = 0; j < 8; j++) {
                float x3 = xv[j];
                float s = bias;
                s = fmaf(w0, x0, s); s = fmaf(w1, x1, s);
                s = fmaf(w2, x2, s); s = fmaf(w3, x3, s);
                float sl = s / (1.f + __expf(-s));
                h16 hi, lo; split_h16(sl, hi, lo);
                Ahi[(i0+j)*XKS + d] = hi;
                Alo[(i0+j)*XKS + d] = lo;
                x0 = x1; x1 = x2; x2 = x3;
            }
        }
        if (d < XK - DINNER) {
            h16 z0 = __float2half(0.f);
            for (int i = 0; i < CHUNK; i++) {
                Ahi[i*XKS + DINNER + d] = z0;
                Alo[i*XKS + DINNER + d] = z0;
            }
        }
    }
    __syncthreads();

    // ---- x_proj GEMM: sdbl[32][64] = A[32][576] @ Wx[64][576]^T (3-term) ----
    // 8 compute warps: ti = warp>>2 (0..1), tj = warp&3 (0..3)
    {
        wmma::fragment<wmma::accumulator,16,16,16,float> accf;
        if (warp < 8) wmma::fill_fragment(accf, 0.f);
        int ti = warp >> 2, tj = warp & 3;
        const h16* gwh = g_wx_hi + (size_t)layer*64*XK;
        const h16* gwl = g_wx_lo + (size_t)layer*64*XK;
        for (int kc = 0; kc < XK/64; kc++) {
            __syncthreads();
            for (int idx = tid; idx < 512; idx += DINNER) {
                int r = idx >> 3, q = (idx & 7)*8;
                *(uint4*)&Wh[r*72 + q] = *(const uint4*)&gwh[(size_t)r*XK + kc*64 + q];
                *(uint4*)&Wl[r*72 + q] = *(const uint4*)&gwl[(size_t)r*XK + kc*64 + q];
            }
            __syncthreads();
            if (warp < 8) {
#pragma unroll
                for (int ks = 0; ks < 64; ks += 16) {
                    wmma::fragment<wmma::matrix_a,16,16,16,h16,wmma::row_major> ah, al;
                    wmma::fragment<wmma::matrix_b,16,16,16,h16,wmma::col_major> bh, bl;
                    wmma::load_matrix_sync(ah, Ahi + ti*16*XKS + kc*64 + ks, XKS);
                    wmma::load_matrix_sync(al, Alo + ti*16*XKS + kc*64 + ks, XKS);
                    wmma::load_matrix_sync(bh, Wh + tj*16*72 + ks, 72);
                    wmma::load_matrix_sync(bl, Wl + tj*16*72 + ks, 72);
                    wmma::mma_sync(accf, ah, bh, accf);
                    wmma::mma_sync(accf, ah, bl, accf);
                    wmma::mma_sync(accf, al, bh, accf);
                }
            }
        }
        __syncthreads();
        if (warp < 8)
            wmma::store_matrix_sync(sdbl + ti*16*68 + tj*16, accf, 68, wmma::mem_row_major);
    }
    __syncthreads();

    // dbl -> global for scan3
    for (int idx = tid; idx < CHUNK*64; idx += DINNER) {
        int i = idx >> 6, j = idx & 63;
        g_dbl2[(size_t)(m0+i)*NX + j] = sdbl[i*68 + j];
    }

    // ---- scan1 phase ----
    {
        float wreg[DTRANK];
#pragma unroll
        for (int r = 0; r < DTRANK; r++)
            wreg[r] = dt_w[(size_t)(layer*DINNER + d)*DTRANK + r];
        float dbias = dt_b[layer*DINNER + d];
        float A2[DSTATE];
#pragma unroll
        for (int n = 0; n < DSTATE; n++)
            A2[n] = g_A2[(size_t)(layer*DINNER + d)*DSTATE + n];
        float ab = A2[0];
        bool fast = true;
#pragma unroll
        for (int n = 1; n < DSTATE; n++)
            fast = fast && (fabsf(A2[n] - (float)(n+1)*ab)
                            <= 1e-4f*fabsf((float)(n+1)*ab) + 1e-6f);

        float h[DSTATE];
#pragma unroll
        for (int n = 0; n < DSTATE; n++) h[n] = 0.f;
        float sumd = 0.f;

        for (int i = 0; i < CHUNK; i++) {
            float sdt = dbias;
#pragma unroll
            for (int r = 0; r < DTRANK; r++) sdt = fmaf(sdbl[i*68 + r], wreg[r], sdt);
            float delta = fmaxf(sdt, 0.f) + log1pf(__expf(-fabsf(sdt)));
            float u = __half2float(Ahi[i*XKS + d]) + __half2float(Alo[i*XKS + d]);
            float du = delta * u;
            if (fast) {
                float e1 = ex2(delta * ab);
                float p = e1;
#pragma unroll
                for (int n = 0; n < DSTATE; n++) {
                    h[n] = fmaf(p, h[n], du * sdbl[i*68 + DTRANK + n]);
                    p *= e1;
                }
            } else {
#pragma unroll
                for (int n = 0; n < DSTATE; n++) {
                    float a = ex2(delta * A2[n]);
                    h[n] = fmaf(a, h[n], du * sdbl[i*68 + DTRANK + n]);
                }
            }
            sumd += delta;
        }
        size_t o = ((size_t)(b*NCHUNK + c)*DINNER + d)*DSTATE;
#pragma unroll
        for (int n = 0; n < DSTATE; n++) {
            g_hend[o + n] = h[n];
            g_P[o + n] = ex2(A2[n] * sumd);
        }
    }
}

__global__ void __launch_bounds__(256) scan2_kernel()
{
    int gw = (blockIdx.x*256 + threadIdx.x) >> 5;
    int lane = threadIdx.x & 31;
    if (gw >= BATCH*(DINNER/2)) return;
    int b = gw / (DINNER/2);
    int dp = gw - b*(DINNER/2);
    float H = 0.f;
    for (int c = 0; c < NCHUNK; c++) {
        size_t o = ((size_t)(b*NCHUNK + c)*DINNER + dp*2)*DSTATE + lane;
        float P = g_P[o];
        float E = g_hend[o];
        g_Hin[o] = H;
        H = fmaf(P, H, E);
    }
}

// ---------------- scan3: inline conv + scan + gate -> yg fp16 (MLP-batched) ----------------
__global__ void __launch_bounds__(DINNER) scan3_kernel(
    const float* __restrict__ conv_w, const float* __restrict__ conv_b,
    const float* __restrict__ dt_w, const float* __restrict__ dt_b,
    const float* __restrict__ D_param, int layer)
{
    int c = blockIdx.x, b = blockIdx.y;
    int d = threadIdx.x;
    __shared__ float sD[CHUNK][NDBL+1];
    int t0 = c*CHUNK;
    int m0 = b*TSEQ + t0;
    for (int idx = d; idx < CHUNK*NDBL; idx += DINNER) {
        int i = idx / NDBL, j = idx - i*NDBL;
        sD[i][j] = g_dbl2[(size_t)(m0+i)*NX + j];
    }
    float wreg[DTRANK];
#pragma unroll
    for (int r = 0; r < DTRANK; r++)
        wreg[r] = dt_w[(size_t)(layer*DINNER + d)*DTRANK + r];
    float dbias = dt_b[layer*DINNER + d];
    float A2[DSTATE];
#pragma unroll
    for (int n = 0; n < DSTATE; n++)
        A2[n] = g_A2[(size_t)(layer*DINNER + d)*DSTATE + n];
    float ab = A2[0];
    bool fast = true;
#pragma unroll
    for (int n = 1; n < DSTATE; n++)
        fast = fast && (fabsf(A2[n] - (float)(n+1)*ab)
                        <= 1e-4f*fabsf((float)(n+1)*ab) + 1e-6f);

    const float* wp = conv_w + (size_t)(layer*DINNER + d)*DCONV;
    float w0 = wp[0], w1 = wp[1], w2 = wp[2], w3 = wp[3];
    float cbias = conv_b[layer*DINNER + d];
    size_t base = (size_t)(b*TSEQ)*(2*DINNER) + d;
    float x0 = (t0-3 >= 0) ? g_xz[base + (size_t)(t0-3)*(2*DINNER)] : 0.f;
    float x1 = (t0-2 >= 0) ? g_xz[base + (size_t)(t0-2)*(2*DINNER)] : 0.f;
    float x2 = (t0-1 >= 0) ? g_xz[base + (size_t)(t0-1)*(2*DINNER)] : 0.f;

    float h[DSTATE];
    size_t oin = ((size_t)(b*NCHUNK + c)*DINNER + d)*DSTATE;
#pragma unroll
    for (int n = 0; n < DSTATE; n++) h[n] = g_Hin[oin + n];
    float Dp = D_param[layer*DINNER + d];
    __syncthreads();

    for (int i0 = 0; i0 < CHUNK; i0 += 8) {
        float xv[8], zv[8];
#pragma unroll
        for (int j = 0; j < 8; j++) {
            size_t rowoff = base + (size_t)(t0+i0+j)*(2*DINNER);
            xv[j] = g_xz[rowoff];
            zv[j] = g_xz[rowoff + DINNER];
        }
#pragma unroll
        for (int j = 0; j < 8; j++) {
            int i = i0 + j;
            int m = m0 + i;
            float x3 = xv[j];
            float cs = cbias;
            cs = fmaf(w0, x0, cs); cs = fmaf(w1, x1, cs);
            cs = fmaf(w2, x2, cs); cs = fmaf(w3, x3, cs);
            float u = cs / (1.f + __expf(-cs));
            x0 = x1; x1 = x2; x2 = x3;

            float sdt = dbias;
#pragma unroll
            for (int r = 0; r < DTRANK; r++) sdt = fmaf(sD[i][r], wreg[r], sdt);
            float delta = fmaxf(sdt, 0.f) + log1pf(__expf(-fabsf(sdt)));
            float du = delta * u;
            float y = 0.f;
            if (fast) {
                float e1 = ex2(delta * ab);
                float p = e1;
#pragma unroll
                for (int n = 0; n < DSTATE; n++) {
                    h[n] = fmaf(p, h[n], du * sD[i][DTRANK + n]);
                    y = fmaf(h[n], sD[i][DTRANK + DSTATE + n], y);
                    p *= e1;
                }
            } else {
#pragma unroll
                for (int n = 0; n < DSTATE; n++) {
                    float a = ex2(delta * A2[n]);
                    h[n] = fmaf(a, h[n], du * sD[i][DTRANK + n]);
                    y = fmaf(h[n], sD[i][DTRANK + DSTATE + n], y);
                }
            }
            float silz = zv[j] / (1.f + __expf(-zv[j]));
            float yg = fmaf(u, Dp, y) * silz;
            g_yg[(size_t)m*DINNER + d] = __float2half_rn(yg);
        }
    }
}

// ---------------- host launcher ----------------
extern "C" void kernel_launch(void* const* d_in, const int* in_sizes, int n_in,
                              void* d_out, int out_size)
{
    (void)in_sizes; (void)n_in; (void)out_size;
    const int*   type_seq = (const int*)  d_in[0];
    const float* time_seq = (const float*)d_in[1];
    const float* temp_seq = (const float*)d_in[2];
    const float* emb      = (const float*)d_in[3];
    const float* norm_w   = (const float*)d_in[4];
    const float* norm_b   = (const float*)d_in[5];
    const float* in_w     = (const float*)d_in[6];
    const float* conv_w   = (const float*)d_in[7];
    const float* conv_b   = (const float*)d_in[8];
    const float* xproj_w  = (const float*)d_in[9];
    const float* dt_w     = (const float*)d_in[10];
    const float* dt_b     = (const float*)d_in[11];
    const float* A_log    = (const float*)d_in[12];
    const float* D_param  = (const float*)d_in[13];
    const float* out_w    = (const float*)d_in[14];
    const float* normf_w  = (const float*)d_in[15];
    const float* normf_b  = (const float*)d_in[16];
    float* out = (float*)d_out;

    float *p_xz, *p_h;
    cudaGetSymbolAddress((void**)&p_xz, g_xz);
    cudaGetSymbolAddress((void**)&p_h,  g_h);
    h16 *p_hn, *p_yg, *p_w1h, *p_w1l, *p_w2h, *p_w2l;
    cudaGetSymbolAddress((void**)&p_hn,  g_hn);
    cudaGetSymbolAddress((void**)&p_yg,  g_yg);
    cudaGetSymbolAddress((void**)&p_w1h, g_w1_hi);
    cudaGetSymbolAddress((void**)&p_w1l, g_w1_lo);
    cudaGetSymbolAddress((void**)&p_w2h, g_w2_hi);
    cudaGetSymbolAddress((void**)&p_w2l, g_w2_lo);

    cudaFuncSetAttribute(gemm_h16,
                         cudaFuncAttributeMaxDynamicSharedMemorySize, GEMM_SMEM);
    cudaFuncSetAttribute(mega1,
                         cudaFuncAttributeMaxDynamicSharedMemorySize, MG_SMEM);

    embed_kernel<<<MROWS, DDIM>>>(type_seq, time_seq, temp_seq, emb);
    prep_all<<<(W1TOT + W2TOT + WXTOT + A2TOT + 255)/256, 256>>>(
        in_w, out_w, xproj_w, A_log);

    for (int l = 0; l < NLAYER; l++) {
        addnorm_kernel<<<MROWS, 128>>>(norm_w + l*DDIM, norm_b + l*DDIM, l > 0);

        gemm_h16<<<dim3((2*DINNER + 127)/128, MROWS/128), 256, GEMM_SMEM>>>(
            p_hn,
            p_w1h + (size_t)l*2*DINNER*KPAD1, p_w1l + (size_t)l*2*DINNER*KPAD1,
            p_xz, MROWS, 2*DINNER, KPAD1);

        mega1<<<dim3(NCHUNK, BATCH), DINNER, MG_SMEM>>>(
            conv_w, conv_b, dt_w, dt_b, l);

        scan2_kernel<<<(BATCH*(DINNER/2)*32 + 255)/256, 256>>>();

        scan3_kernel<<<dim3(NCHUNK, BATCH), DINNER>>>(
            conv_w, conv_b, dt_w, dt_b, D_param, l);

        gemm_h16<<<dim3((DDIM + 127)/128, MROWS/128), 256, GEMM_SMEM>>>(
            p_yg,
            p_w2h + (size_t)l*DDIM*DINNER, p_w2l + (size_t)l*DDIM*DINNER,
            p_h, MROWS, DDIM, DINNER);
    }

    final_kernel<<<BATCH*LQ, 128>>>(normf_w, normf_b, out);
}

// round 14
// speedup vs baseline: 1.2561x; 1.2561x over previous
#include <cuda_runtime.h>
#include <cuda_fp16.h>
#include <math.h>
#include <stdint.h>
#include <mma.h>

using namespace nvcuda;

#define BATCH   4
#define LQ      1024
#define TSEQ    2048
#define DMODEL  256
#define DTIME   16
#define DDIM    272
#define KPAD1   288
#define NLAYER  4
#define DINNER  544
#define DSTATE  16
#define DCONV   4
#define DTRANK  17
#define NDBL    (DTRANK + 2*DSTATE)   // 49
#define MROWS   (BATCH*TSEQ)          // 8192
#define NCHUNK  32
#define CHUNK   (TSEQ/NCHUNK)         // 64
#define XK      576
#define XKS     (XK+8)
#define NX      64

typedef __half h16;

__device__ float g_h   [MROWS*DDIM];
__device__ float g_res [MROWS*DDIM];
__device__ float g_xz  [MROWS*2*DINNER];
__device__ float g_dbl2[MROWS*NX];
__device__ float g_hend[BATCH*NCHUNK*DINNER*DSTATE];
__device__ float g_P   [BATCH*NCHUNK*DINNER*DSTATE];
__device__ float g_Hin [BATCH*NCHUNK*DINNER*DSTATE];
__device__ float g_A2  [NLAYER*DINNER*DSTATE];
__device__ h16 g_hn [MROWS*KPAD1];
__device__ h16 g_yg [MROWS*DINNER];
__device__ h16 g_w1_hi[NLAYER*2*DINNER*KPAD1];
__device__ h16 g_w1_lo[NLAYER*2*DINNER*KPAD1];
__device__ h16 g_w2_hi[NLAYER*DDIM*DINNER];
__device__ h16 g_w2_lo[NLAYER*DDIM*DINNER];
__device__ h16 g_wx_hi[NLAYER*64*XK];
__device__ h16 g_wx_lo[NLAYER*64*XK];

__device__ __forceinline__ float ex2(float x) {
    float y; asm("ex2.approx.ftz.f32 %0, %1;" : "=f"(y) : "f"(x)); return y;
}
__device__ __forceinline__ float softplus_f(float x) {
    // softplus via MUFU: max(x,0) + log(1+exp(-|x|)); __logf abs err ~1e-7 here
    return fmaxf(x, 0.f) + __logf(1.f + __expf(-fabsf(x)));
}
__device__ __forceinline__ float silu_f(float x) {
    return __fdividef(x, 1.f + __expf(-x));
}
__device__ __forceinline__ void split_h16(float v, h16& hi, h16& lo) {
    hi = __float2half_rn(v);
    lo = __float2half_rn(v - __half2float(hi));
}
__device__ __forceinline__ void cp16(uint32_t saddr, const void* g, int srcsz) {
    asm volatile("cp.async.ca.shared.global [%0], [%1], 16, %2;\n"
                 :: "r"(saddr), "l"(g), "r"(srcsz));
}
__device__ __forceinline__ void cp_commit() { asm volatile("cp.async.commit_group;\n"); }
template<int NN> __device__ __forceinline__ void cp_wait() {
    asm volatile("cp.async.wait_group %0;\n" :: "n"(NN));
}

// ---------------- embedding ----------------
__global__ void __launch_bounds__(DDIM) embed_kernel(
    const int* __restrict__ type_seq, const float* __restrict__ time_seq,
    const float* __restrict__ temp_seq, const float* __restrict__ emb)
{
    int row = blockIdx.x;
    int d = threadIdx.x;
    int b = row / TSEQ, t = row % TSEQ;
    float v;
    if (t < LQ) {
        if (d < DMODEL) {
            v = tanhf(emb[(size_t)type_seq[b*LQ + t]*DMODEL + d]);
        } else {
            int j = d - DMODEL;
            int i = j >> 1;
            float div = expf(-0.57564627324851142f * (float)(2*i));
            float arg = time_seq[b*LQ + t] * div;
            v = (j & 1) ? cosf(arg) : sinf(arg);
        }
    } else {
        v = (d < DMODEL) ? 0.f
                         : temp_seq[(size_t)(b*LQ + (t - LQ))*DTIME + (d - DMODEL)];
    }
    g_h[(size_t)row*DDIM + d] = v;
}

// ---------------- one-time prep ----------------
#define W1TOT (NLAYER*2*DINNER*KPAD1)
#define W2TOT (NLAYER*DDIM*DINNER)
#define WXTOT (NLAYER*64*XK)
#define A2TOT (NLAYER*DINNER*DSTATE)
__global__ void __launch_bounds__(256) prep_all(
    const float* __restrict__ in_w, const float* __restrict__ out_w,
    const float* __restrict__ xproj_w, const float* __restrict__ A_log)
{
    int idx = blockIdx.x*256 + threadIdx.x;
    if (idx < W1TOT) {
        const int per = 2*DINNER*KPAD1;
        int l = idx / per, rem = idx - l*per;
        int r = rem / KPAD1, c = rem - r*KPAD1;
        float v = (c < DDIM) ? in_w[((size_t)l*2*DINNER + r)*DDIM + c] : 0.f;
        split_h16(v, g_w1_hi[idx], g_w1_lo[idx]);
    } else if (idx < W1TOT + W2TOT) {
        int j = idx - W1TOT;
        split_h16(out_w[j], g_w2_hi[j], g_w2_lo[j]);
    } else if (idx < W1TOT + W2TOT + WXTOT) {
        int j = idx - W1TOT - W2TOT;
        const int per = 64*XK;
        int l = j / per, rem = j - l*per;
        int r = rem / XK, cc = rem - r*XK;
        float v = (r < NDBL && cc < DINNER)
                ? xproj_w[((size_t)l*NDBL + r)*DINNER + cc] : 0.f;
        split_h16(v, g_wx_hi[j], g_wx_lo[j]);
    } else if (idx < W1TOT + W2TOT + WXTOT + A2TOT) {
        int j = idx - W1TOT - W2TOT - WXTOT;
        g_A2[j] = -__expf(A_log[j]) * 1.4426950408889634f;
    }
}

// ---------------- residual add + layernorm -> fp16 hn ----------------
__global__ void __launch_bounds__(128) addnorm_kernel(
    const float* __restrict__ gamma, const float* __restrict__ beta, int addflag)
{
    int row = blockIdx.x;
    int tid = threadIdx.x;
    float v[3];
    float s = 0.f, s2 = 0.f;
#pragma unroll
    for (int j = 0; j < 3; j++) {
        int d = tid + j*128;
        float x = 0.f;
        if (d < DDIM) {
            x = g_h[(size_t)row*DDIM + d];
            if (addflag) x += g_res[(size_t)row*DDIM + d];
        }
        v[j] = x; s += x; s2 += x*x;
    }
#pragma unroll
    for (int o = 16; o > 0; o >>= 1) {
        s  += __shfl_down_sync(0xffffffffu, s,  o);
        s2 += __shfl_down_sync(0xffffffffu, s2, o);
    }
    __shared__ float ss[4], ss2[4];
    if ((tid & 31) == 0) { ss[tid >> 5] = s; ss2[tid >> 5] = s2; }
    __syncthreads();
    if (tid == 0) {
        float a  = ss[0]+ss[1]+ss[2]+ss[3];
        float a2 = ss2[0]+ss2[1]+ss2[2]+ss2[3];
        float mean = a * (1.f/DDIM);
        float var  = a2 * (1.f/DDIM) - mean*mean;
        ss[0] = mean;
        ss2[0] = rsqrtf(var + 1e-5f);
    }
    __syncthreads();
    float mean = ss[0], rstd = ss2[0];
#pragma unroll
    for (int j = 0; j < 3; j++) {
        int d = tid + j*128;
        if (d < DDIM) {
            g_res[(size_t)row*DDIM + d] = v[j];
            float hn = (v[j]-mean)*rstd*gamma[d] + beta[d];
            g_hn[(size_t)row*KPAD1 + d] = __float2half_rn(hn);
        } else if (d < KPAD1) {
            g_hn[(size_t)row*KPAD1 + d] = __float2half(0.f);
        }
    }
}

// ---------------- final add + layernorm ----------------
__global__ void __launch_bounds__(128) final_kernel(
    const float* __restrict__ gamma, const float* __restrict__ beta,
    float* __restrict__ out)
{
    int rowo = blockIdx.x;
    int tid = threadIdx.x;
    int b = rowo / LQ, t = rowo % LQ;
    int m = b*TSEQ + t;
    float v[3];
    float s = 0.f, s2 = 0.f;
#pragma unroll
    for (int j = 0; j < 3; j++) {
        int d = tid + j*128;
        float x = 0.f;
        if (d < DDIM) x = g_h[(size_t)m*DDIM + d] + g_res[(size_t)m*DDIM + d];
        v[j] = x; s += x; s2 += x*x;
    }
#pragma unroll
    for (int o = 16; o > 0; o >>= 1) {
        s  += __shfl_down_sync(0xffffffffu, s,  o);
        s2 += __shfl_down_sync(0xffffffffu, s2, o);
    }
    __shared__ float ss[4], ss2[4];
    if ((tid & 31) == 0) { ss[tid >> 5] = s; ss2[tid >> 5] = s2; }
    __syncthreads();
    if (tid == 0) {
        float a  = ss[0]+ss[1]+ss[2]+ss[3];
        float a2 = ss2[0]+ss2[1]+ss2[2]+ss2[3];
        float mean = a * (1.f/DDIM);
        float var  = a2 * (1.f/DDIM) - mean*mean;
        ss[0] = mean;
        ss2[0] = rsqrtf(var + 1e-5f);
    }
    __syncthreads();
    float mean = ss[0], rstd = ss2[0];
#pragma unroll
    for (int j = 0; j < 3; j++) {
        int d = tid + j*128;
        if (d < DDIM)
            out[(size_t)rowo*DDIM + d] = (v[j]-mean)*rstd*gamma[d] + beta[d];
    }
}

// ---------------- fp16 2-term GEMM, cp.async 2-stage + slab skip ----------------
#define SPAD 8
#define SROW (32+SPAD)
__global__ void __launch_bounds__(256, 2) gemm_h16(
    const h16* __restrict__ A,
    const h16* __restrict__ Whi, const h16* __restrict__ Wlo,
    float* __restrict__ C, int M, int N, int Kpad)
{
    extern __shared__ h16 sm[];
    int tid = threadIdx.x;
    int warp = tid >> 5;
    int wm = warp >> 2;
    int wn = warp & 3;
    int mb = blockIdx.y * 128;
    int nb = blockIdx.x * 128;
    bool wnvalid = (nb + wn*32) < N;

    int aIdx0 = tid*2, aIdx1 = tid*2 + 1;
    int r0 = aIdx0 >> 2, c0 = (aIdx0 & 3) * 8;
    int r1 = aIdx1 >> 2, c1 = (aIdx1 & 3) * 8;
    int wsz0 = ((nb + r0) < N) ? 16 : 0;
    int wsz1 = ((nb + r1) < N) ? 16 : 0;

    const h16* pA0 = A   + (size_t)(mb + r0)*Kpad + c0;
    const h16* pA1 = A   + (size_t)(mb + r1)*Kpad + c1;
    const h16* pW0 = Whi + (size_t)(nb + r0)*Kpad + c0;
    const h16* pW1 = Whi + (size_t)(nb + r1)*Kpad + c1;
    const h16* pV0 = Wlo + (size_t)(nb + r0)*Kpad + c0;
    const h16* pV1 = Wlo + (size_t)(nb + r1)*Kpad + c1;

    uint32_t sbase = (uint32_t)__cvta_generic_to_shared(sm);
    auto soff = [&](int stage, int arr, int row, int col) -> uint32_t {
        return (uint32_t)((((stage*3 + arr)*128) + row)*SROW + col);
    };
    uint32_t dA0 = soff(0,0,r0,c0), dA1 = soff(0,0,r1,c1);
    uint32_t dW0 = soff(0,1,r0,c0), dW1 = soff(0,1,r1,c1);
    uint32_t dV0 = soff(0,2,r0,c0), dV1 = soff(0,2,r1,c1);
    const uint32_t STG = 3*128*SROW;

    wmma::fragment<wmma::accumulator,16,16,16,float> acc[4][2];
#pragma unroll
    for (int i = 0; i < 4; i++)
#pragma unroll
        for (int j = 0; j < 2; j++) wmma::fill_fragment(acc[i][j], 0.f);

    int ktiles = Kpad >> 5;

    cp16(sbase + 2*dA0, pA0, 16); cp16(sbase + 2*dA1, pA1, 16);
    cp16(sbase + 2*dW0, pW0, wsz0); cp16(sbase + 2*dW1, pW1, wsz1);
    cp16(sbase + 2*dV0, pV0, wsz0); cp16(sbase + 2*dV1, pV1, wsz1);
    cp_commit();

    for (int kt = 0; kt < ktiles; kt++) {
        if (kt + 1 < ktiles) {
            int st = (kt+1) & 1;
            int go = (kt+1) * 32;
            uint32_t so = st * STG;
            cp16(sbase + 2*(dA0+so), pA0 + go, 16); cp16(sbase + 2*(dA1+so), pA1 + go, 16);
            cp16(sbase + 2*(dW0+so), pW0 + go, wsz0); cp16(sbase + 2*(dW1+so), pW1 + go, wsz1);
            cp16(sbase + 2*(dV0+so), pV0 + go, wsz0); cp16(sbase + 2*(dV1+so), pV1 + go, wsz1);
            cp_commit();
            cp_wait<1>();
        } else {
            cp_wait<0>();
        }
        __syncthreads();

        if (wnvalid) {
            const h16* bA   = sm + (size_t)(kt&1)*STG + 0*128*SROW;
            const h16* bWhi = sm + (size_t)(kt&1)*STG + 1*128*SROW;
            const h16* bWlo = sm + (size_t)(kt&1)*STG + 2*128*SROW;
#pragma unroll
            for (int ks = 0; ks < 32; ks += 16) {
                wmma::fragment<wmma::matrix_b,16,16,16,h16,wmma::col_major> bhi[2], blo[2];
#pragma unroll
                for (int j = 0; j < 2; j++) {
                    wmma::load_matrix_sync(bhi[j], bWhi + (wn*32 + j*16)*SROW + ks, SROW);
                    wmma::load_matrix_sync(blo[j], bWlo + (wn*32 + j*16)*SROW + ks, SROW);
                }
#pragma unroll
                for (int i = 0; i < 4; i++) {
                    wmma::fragment<wmma::matrix_a,16,16,16,h16,wmma::row_major> af;
                    wmma::load_matrix_sync(af, bA + (wm*64 + i*16)*SROW + ks, SROW);
#pragma unroll
                    for (int j = 0; j < 2; j++) {
                        wmma::mma_sync(acc[i][j], af, bhi[j], acc[i][j]);
                        wmma::mma_sync(acc[i][j], af, blo[j], acc[i][j]);
                    }
                }
            }
        }
        __syncthreads();
    }
    if (wnvalid) {
#pragma unroll
        for (int i = 0; i < 4; i++)
#pragma unroll
            for (int j = 0; j < 2; j++) {
                int n0 = nb + wn*32 + j*16;
                if (n0 < N)
                    wmma::store_matrix_sync(C + (size_t)(mb + wm*64 + i*16)*N + n0,
                                            acc[i][j], N, wmma::mem_row_major);
            }
    }
}
#define GEMM_SMEM (2*3*128*SROW*2)   // 61440 bytes

// ---------------- mega1: conv + x_proj (3-term fp16 tensor) + scan1 ----------------
#define MG_AHI  0
#define MG_ALO  (CHUNK*XKS*2)
#define MG_WH   (2*CHUNK*XKS*2)
#define MG_WL   (MG_WH + 64*72*2)
#define MG_DBL  (MG_WL + 64*72*2)
#define MG_SMEM (MG_DBL + CHUNK*68*4)
__global__ void __launch_bounds__(DINNER) mega1(
    const float* __restrict__ conv_w, const float* __restrict__ conv_b,
    const float* __restrict__ dt_w, const float* __restrict__ dt_b,
    int layer)
{
    extern __shared__ __align__(16) char smx[];
    h16*  Ahi  = (h16*)(smx + MG_AHI);
    h16*  Alo  = (h16*)(smx + MG_ALO);
    h16*  Wh   = (h16*)(smx + MG_WH);
    h16*  Wl   = (h16*)(smx + MG_WL);
    float* sdbl = (float*)(smx + MG_DBL);

    int c = blockIdx.x, b = blockIdx.y;
    int tid = threadIdx.x;
    int d = tid;
    int warp = tid >> 5;
    int t0 = c*CHUNK;
    int m0 = b*TSEQ + t0;

    // ---- conv phase (MLP-batched loads) ----
    {
        const float* wp = conv_w + (size_t)(layer*DINNER + d)*DCONV;
        float w0 = wp[0], w1 = wp[1], w2 = wp[2], w3 = wp[3];
        float bias = conv_b[layer*DINNER + d];
        size_t base = (size_t)(b*TSEQ)*(2*DINNER) + d;
        float x0 = (t0-3 >= 0) ? g_xz[base + (size_t)(t0-3)*(2*DINNER)] : 0.f;
        float x1 = (t0-2 >= 0) ? g_xz[base + (size_t)(t0-2)*(2*DINNER)] : 0.f;
        float x2 = (t0-1 >= 0) ? g_xz[base + (size_t)(t0-1)*(2*DINNER)] : 0.f;
        for (int i0 = 0; i0 < CHUNK; i0 += 8) {
            float xv[8];
#pragma unroll
            for (int j = 0; j < 8; j++)
                xv[j] = g_xz[base + (size_t)(t0+i0+j)*(2*DINNER)];
#pragma unroll
            for (int j = 0; j < 8; j++) {
                float x3 = xv[j];
                float s = bias;
                s = fmaf(w0, x0, s); s = fmaf(w1, x1, s);
                s = fmaf(w2, x2, s); s = fmaf(w3, x3, s);
                float sl = silu_f(s);
                h16 hi, lo; split_h16(sl, hi, lo);
                Ahi[(i0+j)*XKS + d] = hi;
                Alo[(i0+j)*XKS + d] = lo;
                x0 = x1; x1 = x2; x2 = x3;
            }
        }
        if (d < XK - DINNER) {
            h16 z0 = __float2half(0.f);
            for (int i = 0; i < CHUNK; i++) {
                Ahi[i*XKS + DINNER + d] = z0;
                Alo[i*XKS + DINNER + d] = z0;
            }
        }
    }
    __syncthreads();

    // ---- x_proj GEMM: sdbl[64][64] = A[64][576] @ Wx[64][576]^T (3-term) ----
    {
        wmma::fragment<wmma::accumulator,16,16,16,float> accf;
        if (warp < 16) wmma::fill_fragment(accf, 0.f);
        int ti = warp >> 2, tj = warp & 3;
        const h16* gwh = g_wx_hi + (size_t)layer*64*XK;
        const h16* gwl = g_wx_lo + (size_t)layer*64*XK;
        for (int kc = 0; kc < XK/64; kc++) {
            __syncthreads();
            for (int idx = tid; idx < 512; idx += DINNER) {
                int r = idx >> 3, q = (idx & 7)*8;
                *(uint4*)&Wh[r*72 + q] = *(const uint4*)&gwh[(size_t)r*XK + kc*64 + q];
                *(uint4*)&Wl[r*72 + q] = *(const uint4*)&gwl[(size_t)r*XK + kc*64 + q];
            }
            __syncthreads();
            if (warp < 16) {
#pragma unroll
                for (int ks = 0; ks < 64; ks += 16) {
                    wmma::fragment<wmma::matrix_a,16,16,16,h16,wmma::row_major> ah, al;
                    wmma::fragment<wmma::matrix_b,16,16,16,h16,wmma::col_major> bh, bl;
                    wmma::load_matrix_sync(ah, Ahi + ti*16*XKS + kc*64 + ks, XKS);
                    wmma::load_matrix_sync(al, Alo + ti*16*XKS + kc*64 + ks, XKS);
                    wmma::load_matrix_sync(bh, Wh + tj*16*72 + ks, 72);
                    wmma::load_matrix_sync(bl, Wl + tj*16*72 + ks, 72);
                    wmma::mma_sync(accf, ah, bh, accf);
                    wmma::mma_sync(accf, ah, bl, accf);
                    wmma::mma_sync(accf, al, bh, accf);
                }
            }
        }
        __syncthreads();
        if (warp < 16)
            wmma::store_matrix_sync(sdbl + ti*16*68 + tj*16, accf, 68, wmma::mem_row_major);
    }
    __syncthreads();

    // dbl -> global for scan3
    for (int idx = tid; idx < CHUNK*64; idx += DINNER) {
        int i = idx >> 6, j = idx & 63;
        g_dbl2[(size_t)(m0+i)*NX + j] = sdbl[i*68 + j];
    }

    // ---- scan1 phase ----
    {
        float wreg[DTRANK];
#pragma unroll
        for (int r = 0; r < DTRANK; r++)
            wreg[r] = dt_w[(size_t)(layer*DINNER + d)*DTRANK + r];
        float dbias = dt_b[layer*DINNER + d];
        float A2[DSTATE];
#pragma unroll
        for (int n = 0; n < DSTATE; n++)
            A2[n] = g_A2[(size_t)(layer*DINNER + d)*DSTATE + n];
        float ab = A2[0];
        bool fast = true;
#pragma unroll
        for (int n = 1; n < DSTATE; n++)
            fast = fast && (fabsf(A2[n] - (float)(n+1)*ab)
                            <= 1e-4f*fabsf((float)(n+1)*ab) + 1e-6f);

        float h[DSTATE];
#pragma unroll
        for (int n = 0; n < DSTATE; n++) h[n] = 0.f;
        float sumd = 0.f;

        for (int i = 0; i < CHUNK; i++) {
            float sdt = dbias;
#pragma unroll
            for (int r = 0; r < DTRANK; r++) sdt = fmaf(sdbl[i*68 + r], wreg[r], sdt);
            float delta = softplus_f(sdt);
            float u = __half2float(Ahi[i*XKS + d]) + __half2float(Alo[i*XKS + d]);
            float du = delta * u;
            if (fast) {
                float e1 = ex2(delta * ab);
                float p = e1;
#pragma unroll
                for (int n = 0; n < DSTATE; n++) {
                    h[n] = fmaf(p, h[n], du * sdbl[i*68 + DTRANK + n]);
                    p *= e1;
                }
            } else {
#pragma unroll
                for (int n = 0; n < DSTATE; n++) {
                    float a = ex2(delta * A2[n]);
                    h[n] = fmaf(a, h[n], du * sdbl[i*68 + DTRANK + n]);
                }
            }
            sumd += delta;
        }
        size_t o = ((size_t)(b*NCHUNK + c)*DINNER + d)*DSTATE;
#pragma unroll
        for (int n = 0; n < DSTATE; n++) {
            g_hend[o + n] = h[n];
            g_P[o + n] = ex2(A2[n] * sumd);
        }
    }
}

__global__ void __launch_bounds__(256) scan2_kernel()
{
    int gw = (blockIdx.x*256 + threadIdx.x) >> 5;
    int lane = threadIdx.x & 31;
    if (gw >= BATCH*(DINNER/2)) return;
    int b = gw / (DINNER/2);
    int dp = gw - b*(DINNER/2);
    float H = 0.f;
    for (int c = 0; c < NCHUNK; c++) {
        size_t o = ((size_t)(b*NCHUNK + c)*DINNER + dp*2)*DSTATE + lane;
        float P = g_P[o];
        float E = g_hend[o];
        g_Hin[o] = H;
        H = fmaf(P, H, E);
    }
}

// ---------------- scan3: inline conv + scan + gate -> yg fp16 (MLP-batched) ----------------
__global__ void __launch_bounds__(DINNER) scan3_kernel(
    const float* __restrict__ conv_w, const float* __restrict__ conv_b,
    const float* __restrict__ dt_w, const float* __restrict__ dt_b,
    const float* __restrict__ D_param, int layer)
{
    int c = blockIdx.x, b = blockIdx.y;
    int d = threadIdx.x;
    __shared__ float sD[CHUNK][NDBL+1];
    int t0 = c*CHUNK;
    int m0 = b*TSEQ + t0;
    for (int idx = d; idx < CHUNK*NDBL; idx += DINNER) {
        int i = idx / NDBL, j = idx - i*NDBL;
        sD[i][j] = g_dbl2[(size_t)(m0+i)*NX + j];
    }
    float wreg[DTRANK];
#pragma unroll
    for (int r = 0; r < DTRANK; r++)
        wreg[r] = dt_w[(size_t)(layer*DINNER + d)*DTRANK + r];
    float dbias = dt_b[layer*DINNER + d];
    float A2[DSTATE];
#pragma unroll
    for (int n = 0; n < DSTATE; n++)
        A2[n] = g_A2[(size_t)(layer*DINNER + d)*DSTATE + n];
    float ab = A2[0];
    bool fast = true;
#pragma unroll
    for (int n = 1; n < DSTATE; n++)
        fast = fast && (fabsf(A2[n] - (float)(n+1)*ab)
                        <= 1e-4f*fabsf((float)(n+1)*ab) + 1e-6f);

    const float* wp = conv_w + (size_t)(layer*DINNER + d)*DCONV;
    float w0 = wp[0], w1 = wp[1], w2 = wp[2], w3 = wp[3];
    float cbias = conv_b[layer*DINNER + d];
    size_t base = (size_t)(b*TSEQ)*(2*DINNER) + d;
    float x0 = (t0-3 >= 0) ? g_xz[base + (size_t)(t0-3)*(2*DINNER)] : 0.f;
    float x1 = (t0-2 >= 0) ? g_xz[base + (size_t)(t0-2)*(2*DINNER)] : 0.f;
    float x2 = (t0-1 >= 0) ? g_xz[base + (size_t)(t0-1)*(2*DINNER)] : 0.f;

    float h[DSTATE];
    size_t oin = ((size_t)(b*NCHUNK + c)*DINNER + d)*DSTATE;
#pragma unroll
    for (int n = 0; n < DSTATE; n++) h[n] = g_Hin[oin + n];
    float Dp = D_param[layer*DINNER + d];
    __syncthreads();

    for (int i0 = 0; i0 < CHUNK; i0 += 8) {
        float xv[8], zv[8];
#pragma unroll
        for (int j = 0; j < 8; j++) {
            size_t rowoff = base + (size_t)(t0+i0+j)*(2*DINNER);
            xv[j] = g_xz[rowoff];
            zv[j] = g_xz[rowoff + DINNER];
        }
#pragma unroll
        for (int j = 0; j < 8; j++) {
            int i = i0 + j;
            int m = m0 + i;
            float x3 = xv[j];
            float cs = cbias;
            cs = fmaf(w0, x0, cs); cs = fmaf(w1, x1, cs);
            cs = fmaf(w2, x2, cs); cs = fmaf(w3, x3, cs);
            float u = silu_f(cs);
            x0 = x1; x1 = x2; x2 = x3;

            float sdt = dbias;
#pragma unroll
            for (int r = 0; r < DTRANK; r++) sdt = fmaf(sD[i][r], wreg[r], sdt);
            float delta = softplus_f(sdt);
            float du = delta * u;
            float y = 0.f;
            if (fast) {
                float e1 = ex2(delta * ab);
                float p = e1;
#pragma unroll
                for (int n = 0; n < DSTATE; n++) {
                    h[n] = fmaf(p, h[n], du * sD[i][DTRANK + n]);
                    y = fmaf(h[n], sD[i][DTRANK + DSTATE + n], y);
                    p *= e1;
                }
            } else {
#pragma unroll
                for (int n = 0; n < DSTATE; n++) {
                    float a = ex2(delta * A2[n]);
                    h[n] = fmaf(a, h[n], du * sD[i][DTRANK + n]);
                    y = fmaf(h[n], sD[i][DTRANK + DSTATE + n], y);
                }
            }
            float silz = silu_f(zv[j]);
            float yg = fmaf(u, Dp, y) * silz;
            g_yg[(size_t)m*DINNER + d] = __float2half_rn(yg);
        }
    }
}

// ---------------- host launcher ----------------
extern "C" void kernel_launch(void* const* d_in, const int* in_sizes, int n_in,
                              void* d_out, int out_size)
{
    (void)in_sizes; (void)n_in; (void)out_size;
    const int*   type_seq = (const int*)  d_in[0];
    const float* time_seq = (const float*)d_in[1];
    const float* temp_seq = (const float*)d_in[2];
    const float* emb      = (const float*)d_in[3];
    const float* norm_w   = (const float*)d_in[4];
    const float* norm_b   = (const float*)d_in[5];
    const float* in_w     = (const float*)d_in[6];
    const float* conv_w   = (const float*)d_in[7];
    const float* conv_b   = (const float*)d_in[8];
    const float* xproj_w  = (const float*)d_in[9];
    const float* dt_w     = (const float*)d_in[10];
    const float* dt_b     = (const float*)d_in[11];
    const float* A_log    = (const float*)d_in[12];
    const float* D_param  = (const float*)d_in[13];
    const float* out_w    = (const float*)d_in[14];
    const float* normf_w  = (const float*)d_in[15];
    const float* normf_b  = (const float*)d_in[16];
    float* out = (float*)d_out;

    float *p_xz, *p_h;
    cudaGetSymbolAddress((void**)&p_xz, g_xz);
    cudaGetSymbolAddress((void**)&p_h,  g_h);
    h16 *p_hn, *p_yg, *p_w1h, *p_w1l, *p_w2h, *p_w2l;
    cudaGetSymbolAddress((void**)&p_hn,  g_hn);
    cudaGetSymbolAddress((void**)&p_yg,  g_yg);
    cudaGetSymbolAddress((void**)&p_w1h, g_w1_hi);
    cudaGetSymbolAddress((void**)&p_w1l, g_w1_lo);
    cudaGetSymbolAddress((void**)&p_w2h, g_w2_hi);
    cudaGetSymbolAddress((void**)&p_w2l, g_w2_lo);

    cudaFuncSetAttribute(gemm_h16,
                         cudaFuncAttributeMaxDynamicSharedMemorySize, GEMM_SMEM);
    cudaFuncSetAttribute(mega1,
                         cudaFuncAttributeMaxDynamicSharedMemorySize, MG_SMEM);

    embed_kernel<<<MROWS, DDIM>>>(type_seq, time_seq, temp_seq, emb);
    prep_all<<<(W1TOT + W2TOT + WXTOT + A2TOT + 255)/256, 256>>>(
        in_w, out_w, xproj_w, A_log);

    for (int l = 0; l < NLAYER; l++) {
        addnorm_kernel<<<MROWS, 128>>>(norm_w + l*DDIM, norm_b + l*DDIM, l > 0);

        gemm_h16<<<dim3((2*DINNER + 127)/128, MROWS/128), 256, GEMM_SMEM>>>(
            p_hn,
            p_w1h + (size_t)l*2*DINNER*KPAD1, p_w1l + (size_t)l*2*DINNER*KPAD1,
            p_xz, MROWS, 2*DINNER, KPAD1);

        mega1<<<dim3(NCHUNK, BATCH), DINNER, MG_SMEM>>>(
            conv_w, conv_b, dt_w, dt_b, l);

        scan2_kernel<<<(BATCH*(DINNER/2)*32 + 255)/256, 256>>>();

        scan3_kernel<<<dim3(NCHUNK, BATCH), DINNER>>>(
            conv_w, conv_b, dt_w, dt_b, D_param, l);

        gemm_h16<<<dim3((DDIM + 127)/128, MROWS/128), 256, GEMM_SMEM>>>(
            p_yg,
            p_w2h + (size_t)l*DDIM*DINNER, p_w2l + (size_t)l*DDIM*DINNER,
            p_h, MROWS, DDIM, DINNER);
    }

    final_kernel<<<BATCH*LQ, 128>>>(normf_w, normf_b, out);
}

// round 15
// speedup vs baseline: 1.2607x; 1.0037x over previous
#include <cuda_runtime.h>
#include <cuda_fp16.h>
#include <math.h>
#include <stdint.h>
#include <mma.h>

using namespace nvcuda;

#define BATCH   4
#define LQ      1024
#define TSEQ    2048
#define DMODEL  256
#define DTIME   16
#define DDIM    272
#define KPAD1   288
#define NLAYER  4
#define DINNER  544
#define DSTATE  16
#define DCONV   4
#define DTRANK  17
#define NDBL    (DTRANK + 2*DSTATE)   // 49
#define MROWS   (BATCH*TSEQ)          // 8192
#define NCHUNK  32
#define CHUNK   (TSEQ/NCHUNK)         // 64
#define XK      576
#define XKS     (XK+8)
#define NX      64

typedef __half h16;

__device__ float g_h   [MROWS*DDIM];
__device__ float g_res [MROWS*DDIM];
__device__ float g_xz  [MROWS*2*DINNER];
__device__ float g_dbl2[MROWS*NX];
__device__ float g_hend[BATCH*NCHUNK*DINNER*DSTATE];
__device__ float g_P   [BATCH*NCHUNK*DINNER*DSTATE];
__device__ float g_Hin [BATCH*NCHUNK*DINNER*DSTATE];
__device__ float g_A2  [NLAYER*DINNER*DSTATE];
__device__ __half2 g_u2[MROWS*DINNER];   // u split (hi,lo) from mega1 conv
__device__ h16 g_hn [MROWS*KPAD1];
__device__ h16 g_yg [MROWS*DINNER];
__device__ h16 g_w1_hi[NLAYER*2*DINNER*KPAD1];
__device__ h16 g_w1_lo[NLAYER*2*DINNER*KPAD1];
__device__ h16 g_w2_hi[NLAYER*DDIM*DINNER];
__device__ h16 g_w2_lo[NLAYER*DDIM*DINNER];
__device__ h16 g_wx_hi[NLAYER*64*XK];
__device__ h16 g_wx_lo[NLAYER*64*XK];

__device__ __forceinline__ float ex2(float x) {
    float y; asm("ex2.approx.ftz.f32 %0, %1;" : "=f"(y) : "f"(x)); return y;
}
__device__ __forceinline__ float softplus_f(float x) {
    return fmaxf(x, 0.f) + __logf(1.f + __expf(-fabsf(x)));
}
__device__ __forceinline__ float silu_f(float x) {
    return __fdividef(x, 1.f + __expf(-x));
}
__device__ __forceinline__ void split_h16(float v, h16& hi, h16& lo) {
    hi = __float2half_rn(v);
    lo = __float2half_rn(v - __half2float(hi));
}
__device__ __forceinline__ void cp16(uint32_t saddr, const void* g, int srcsz) {
    asm volatile("cp.async.ca.shared.global [%0], [%1], 16, %2;\n"
                 :: "r"(saddr), "l"(g), "r"(srcsz));
}
__device__ __forceinline__ void cp_commit() { asm volatile("cp.async.commit_group;\n"); }
template<int NN> __device__ __forceinline__ void cp_wait() {
    asm volatile("cp.async.wait_group %0;\n" :: "n"(NN));
}

// ---------------- embedding ----------------
__global__ void __launch_bounds__(DDIM) embed_kernel(
    const int* __restrict__ type_seq, const float* __restrict__ time_seq,
    const float* __restrict__ temp_seq, const float* __restrict__ emb)
{
    int row = blockIdx.x;
    int d = threadIdx.x;
    int b = row / TSEQ, t = row % TSEQ;
    float v;
    if (t < LQ) {
        if (d < DMODEL) {
            v = tanhf(emb[(size_t)type_seq[b*LQ + t]*DMODEL + d]);
        } else {
            int j = d - DMODEL;
            int i = j >> 1;
            float div = expf(-0.57564627324851142f * (float)(2*i));
            float arg = time_seq[b*LQ + t] * div;
            v = (j & 1) ? cosf(arg) : sinf(arg);
        }
    } else {
        v = (d < DMODEL) ? 0.f
                         : temp_seq[(size_t)(b*LQ + (t - LQ))*DTIME + (d - DMODEL)];
    }
    g_h[(size_t)row*DDIM + d] = v;
}

// ---------------- one-time prep ----------------
#define W1TOT (NLAYER*2*DINNER*KPAD1)
#define W2TOT (NLAYER*DDIM*DINNER)
#define WXTOT (NLAYER*64*XK)
#define A2TOT (NLAYER*DINNER*DSTATE)
__global__ void __launch_bounds__(256) prep_all(
    const float* __restrict__ in_w, const float* __restrict__ out_w,
    const float* __restrict__ xproj_w, const float* __restrict__ A_log)
{
    int idx = blockIdx.x*256 + threadIdx.x;
    if (idx < W1TOT) {
        const int per = 2*DINNER*KPAD1;
        int l = idx / per, rem = idx - l*per;
        int r = rem / KPAD1, c = rem - r*KPAD1;
        float v = (c < DDIM) ? in_w[((size_t)l*2*DINNER + r)*DDIM + c] : 0.f;
        split_h16(v, g_w1_hi[idx], g_w1_lo[idx]);
    } else if (idx < W1TOT + W2TOT) {
        int j = idx - W1TOT;
        split_h16(out_w[j], g_w2_hi[j], g_w2_lo[j]);
    } else if (idx < W1TOT + W2TOT + WXTOT) {
        int j = idx - W1TOT - W2TOT;
        const int per = 64*XK;
        int l = j / per, rem = j - l*per;
        int r = rem / XK, cc = rem - r*XK;
        float v = (r < NDBL && cc < DINNER)
                ? xproj_w[((size_t)l*NDBL + r)*DINNER + cc] : 0.f;
        split_h16(v, g_wx_hi[j], g_wx_lo[j]);
    } else if (idx < W1TOT + W2TOT + WXTOT + A2TOT) {
        int j = idx - W1TOT - W2TOT - WXTOT;
        g_A2[j] = -__expf(A_log[j]) * 1.4426950408889634f;
    }
}

// ---------------- residual add + layernorm -> fp16 hn ----------------
__global__ void __launch_bounds__(128) addnorm_kernel(
    const float* __restrict__ gamma, const float* __restrict__ beta, int addflag)
{
    int row = blockIdx.x;
    int tid = threadIdx.x;
    float v[3];
    float s = 0.f, s2 = 0.f;
#pragma unroll
    for (int j = 0; j < 3; j++) {
        int d = tid + j*128;
        float x = 0.f;
        if (d < DDIM) {
            x = g_h[(size_t)row*DDIM + d];
            if (addflag) x += g_res[(size_t)row*DDIM + d];
        }
        v[j] = x; s += x; s2 += x*x;
    }
#pragma unroll
    for (int o = 16; o > 0; o >>= 1) {
        s  += __shfl_down_sync(0xffffffffu, s,  o);
        s2 += __shfl_down_sync(0xffffffffu, s2, o);
    }
    __shared__ float ss[4], ss2[4];
    if ((tid & 31) == 0) { ss[tid >> 5] = s; ss2[tid >> 5] = s2; }
    __syncthreads();
    if (tid == 0) {
        float a  = ss[0]+ss[1]+ss[2]+ss[3];
        float a2 = ss2[0]+ss2[1]+ss2[2]+ss2[3];
        float mean = a * (1.f/DDIM);
        float var  = a2 * (1.f/DDIM) - mean*mean;
        ss[0] = mean;
        ss2[0] = rsqrtf(var + 1e-5f);
    }
    __syncthreads();
    float mean = ss[0], rstd = ss2[0];
#pragma unroll
    for (int j = 0; j < 3; j++) {
        int d = tid + j*128;
        if (d < DDIM) {
            g_res[(size_t)row*DDIM + d] = v[j];
            float hn = (v[j]-mean)*rstd*gamma[d] + beta[d];
            g_hn[(size_t)row*KPAD1 + d] = __float2half_rn(hn);
        } else if (d < KPAD1) {
            g_hn[(size_t)row*KPAD1 + d] = __float2half(0.f);
        }
    }
}

// ---------------- final add + layernorm ----------------
__global__ void __launch_bounds__(128) final_kernel(
    const float* __restrict__ gamma, const float* __restrict__ beta,
    float* __restrict__ out)
{
    int rowo = blockIdx.x;
    int tid = threadIdx.x;
    int b = rowo / LQ, t = rowo % LQ;
    int m = b*TSEQ + t;
    float v[3];
    float s = 0.f, s2 = 0.f;
#pragma unroll
    for (int j = 0; j < 3; j++) {
        int d = tid + j*128;
        float x = 0.f;
        if (d < DDIM) x = g_h[(size_t)m*DDIM + d] + g_res[(size_t)m*DDIM + d];
        v[j] = x; s += x; s2 += x*x;
    }
#pragma unroll
    for (int o = 16; o > 0; o >>= 1) {
        s  += __shfl_down_sync(0xffffffffu, s,  o);
        s2 += __shfl_down_sync(0xffffffffu, s2, o);
    }
    __shared__ float ss[4], ss2[4];
    if ((tid & 31) == 0) { ss[tid >> 5] = s; ss2[tid >> 5] = s2; }
    __syncthreads();
    if (tid == 0) {
        float a  = ss[0]+ss[1]+ss[2]+ss[3];
        float a2 = ss2[0]+ss2[1]+ss2[2]+ss2[3];
        float mean = a * (1.f/DDIM);
        float var  = a2 * (1.f/DDIM) - mean*mean;
        ss[0] = mean;
        ss2[0] = rsqrtf(var + 1e-5f);
    }
    __syncthreads();
    float mean = ss[0], rstd = ss2[0];
#pragma unroll
    for (int j = 0; j < 3; j++) {
        int d = tid + j*128;
        if (d < DDIM)
            out[(size_t)rowo*DDIM + d] = (v[j]-mean)*rstd*gamma[d] + beta[d];
    }
}

// ---------------- fp16 2-term GEMM, cp.async 2-stage + slab skip ----------------
#define SPAD 8
#define SROW (32+SPAD)
__global__ void __launch_bounds__(256, 2) gemm_h16(
    const h16* __restrict__ A,
    const h16* __restrict__ Whi, const h16* __restrict__ Wlo,
    float* __restrict__ C, int M, int N, int Kpad)
{
    extern __shared__ h16 sm[];
    int tid = threadIdx.x;
    int warp = tid >> 5;
    int wm = warp >> 2;
    int wn = warp & 3;
    int mb = blockIdx.y * 128;
    int nb = blockIdx.x * 128;
    bool wnvalid = (nb + wn*32) < N;

    int aIdx0 = tid*2, aIdx1 = tid*2 + 1;
    int r0 = aIdx0 >> 2, c0 = (aIdx0 & 3) * 8;
    int r1 = aIdx1 >> 2, c1 = (aIdx1 & 3) * 8;
    int wsz0 = ((nb + r0) < N) ? 16 : 0;
    int wsz1 = ((nb + r1) < N) ? 16 : 0;

    const h16* pA0 = A   + (size_t)(mb + r0)*Kpad + c0;
    const h16* pA1 = A   + (size_t)(mb + r1)*Kpad + c1;
    const h16* pW0 = Whi + (size_t)(nb + r0)*Kpad + c0;
    const h16* pW1 = Whi + (size_t)(nb + r1)*Kpad + c1;
    const h16* pV0 = Wlo + (size_t)(nb + r0)*Kpad + c0;
    const h16* pV1 = Wlo + (size_t)(nb + r1)*Kpad + c1;

    uint32_t sbase = (uint32_t)__cvta_generic_to_shared(sm);
    auto soff = [&](int stage, int arr, int row, int col) -> uint32_t {
        return (uint32_t)((((stage*3 + arr)*128) + row)*SROW + col);
    };
    uint32_t dA0 = soff(0,0,r0,c0), dA1 = soff(0,0,r1,c1);
    uint32_t dW0 = soff(0,1,r0,c0), dW1 = soff(0,1,r1,c1);
    uint32_t dV0 = soff(0,2,r0,c0), dV1 = soff(0,2,r1,c1);
    const uint32_t STG = 3*128*SROW;

    wmma::fragment<wmma::accumulator,16,16,16,float> acc[4][2];
#pragma unroll
    for (int i = 0; i < 4; i++)
#pragma unroll
        for (int j = 0; j < 2; j++) wmma::fill_fragment(acc[i][j], 0.f);

    int ktiles = Kpad >> 5;

    cp16(sbase + 2*dA0, pA0, 16); cp16(sbase + 2*dA1, pA1, 16);
    cp16(sbase + 2*dW0, pW0, wsz0); cp16(sbase + 2*dW1, pW1, wsz1);
    cp16(sbase + 2*dV0, pV0, wsz0); cp16(sbase + 2*dV1, pV1, wsz1);
    cp_commit();

    for (int kt = 0; kt < ktiles; kt++) {
        if (kt + 1 < ktiles) {
            int st = (kt+1) & 1;
            int go = (kt+1) * 32;
            uint32_t so = st * STG;
            cp16(sbase + 2*(dA0+so), pA0 + go, 16); cp16(sbase + 2*(dA1+so), pA1 + go, 16);
            cp16(sbase + 2*(dW0+so), pW0 + go, wsz0); cp16(sbase + 2*(dW1+so), pW1 + go, wsz1);
            cp16(sbase + 2*(dV0+so), pV0 + go, wsz0); cp16(sbase + 2*(dV1+so), pV1 + go, wsz1);
            cp_commit();
            cp_wait<1>();
        } else {
            cp_wait<0>();
        }
        __syncthreads();

        if (wnvalid) {
            const h16* bA   = sm + (size_t)(kt&1)*STG + 0*128*SROW;
            const h16* bWhi = sm + (size_t)(kt&1)*STG + 1*128*SROW;
            const h16* bWlo = sm + (size_t)(kt&1)*STG + 2*128*SROW;
#pragma unroll
            for (int ks = 0; ks < 32; ks += 16) {
                wmma::fragment<wmma::matrix_b,16,16,16,h16,wmma::col_major> bhi[2], blo[2];
#pragma unroll
                for (int j = 0; j < 2; j++) {
                    wmma::load_matrix_sync(bhi[j], bWhi + (wn*32 + j*16)*SROW + ks, SROW);
                    wmma::load_matrix_sync(blo[j], bWlo + (wn*32 + j*16)*SROW + ks, SROW);
                }
#pragma unroll
                for (int i = 0; i < 4; i++) {
                    wmma::fragment<wmma::matrix_a,16,16,16,h16,wmma::row_major> af;
                    wmma::load_matrix_sync(af, bA + (wm*64 + i*16)*SROW + ks, SROW);
#pragma unroll
                    for (int j = 0; j < 2; j++) {
                        wmma::mma_sync(acc[i][j], af, bhi[j], acc[i][j]);
                        wmma::mma_sync(acc[i][j], af, blo[j], acc[i][j]);
                    }
                }
            }
        }
        __syncthreads();
    }
    if (wnvalid) {
#pragma unroll
        for (int i = 0; i < 4; i++)
#pragma unroll
            for (int j = 0; j < 2; j++) {
                int n0 = nb + wn*32 + j*16;
                if (n0 < N)
                    wmma::store_matrix_sync(C + (size_t)(mb + wm*64 + i*16)*N + n0,
                                            acc[i][j], N, wmma::mem_row_major);
            }
    }
}
#define GEMM_SMEM (2*3*128*SROW*2)   // 61440 bytes

// ---------------- mega1: conv + x_proj (3-term fp16 tensor) + scan1 ----------------
#define MG_AHI  0
#define MG_ALO  (CHUNK*XKS*2)
#define MG_WH   (2*CHUNK*XKS*2)
#define MG_WL   (MG_WH + 64*72*2)
#define MG_DBL  (MG_WL + 64*72*2)
#define MG_SMEM (MG_DBL + CHUNK*68*4)
__global__ void __launch_bounds__(DINNER) mega1(
    const float* __restrict__ conv_w, const float* __restrict__ conv_b,
    const float* __restrict__ dt_w, const float* __restrict__ dt_b,
    int layer)
{
    extern __shared__ __align__(16) char smx[];
    h16*  Ahi  = (h16*)(smx + MG_AHI);
    h16*  Alo  = (h16*)(smx + MG_ALO);
    h16*  Wh   = (h16*)(smx + MG_WH);
    h16*  Wl   = (h16*)(smx + MG_WL);
    float* sdbl = (float*)(smx + MG_DBL);

    int c = blockIdx.x, b = blockIdx.y;
    int tid = threadIdx.x;
    int d = tid;
    int warp = tid >> 5;
    int t0 = c*CHUNK;
    int m0 = b*TSEQ + t0;

    // ---- conv phase (MLP-batched loads); also export u split to global ----
    {
        const float* wp = conv_w + (size_t)(layer*DINNER + d)*DCONV;
        float w0 = wp[0], w1 = wp[1], w2 = wp[2], w3 = wp[3];
        float bias = conv_b[layer*DINNER + d];
        size_t base = (size_t)(b*TSEQ)*(2*DINNER) + d;
        float x0 = (t0-3 >= 0) ? g_xz[base + (size_t)(t0-3)*(2*DINNER)] : 0.f;
        float x1 = (t0-2 >= 0) ? g_xz[base + (size_t)(t0-2)*(2*DINNER)] : 0.f;
        float x2 = (t0-1 >= 0) ? g_xz[base + (size_t)(t0-1)*(2*DINNER)] : 0.f;
        for (int i0 = 0; i0 < CHUNK; i0 += 8) {
            float xv[8];
#pragma unroll
            for (int j = 0; j < 8; j++)
                xv[j] = g_xz[base + (size_t)(t0+i0+j)*(2*DINNER)];
#pragma unroll
            for (int j = 0; j < 8; j++) {
                float x3 = xv[j];
                float s = bias;
                s = fmaf(w0, x0, s); s = fmaf(w1, x1, s);
                s = fmaf(w2, x2, s); s = fmaf(w3, x3, s);
                float sl = silu_f(s);
                h16 hi, lo; split_h16(sl, hi, lo);
                Ahi[(i0+j)*XKS + d] = hi;
                Alo[(i0+j)*XKS + d] = lo;
                g_u2[(size_t)(m0+i0+j)*DINNER + d] = __halves2half2(hi, lo);
                x0 = x1; x1 = x2; x2 = x3;
            }
        }
        if (d < XK - DINNER) {
            h16 z0 = __float2half(0.f);
            for (int i = 0; i < CHUNK; i++) {
                Ahi[i*XKS + DINNER + d] = z0;
                Alo[i*XKS + DINNER + d] = z0;
            }
        }
    }
    __syncthreads();

    // ---- x_proj GEMM: sdbl[64][64] = A[64][576] @ Wx[64][576]^T (3-term) ----
    {
        wmma::fragment<wmma::accumulator,16,16,16,float> accf;
        if (warp < 16) wmma::fill_fragment(accf, 0.f);
        int ti = warp >> 2, tj = warp & 3;
        const h16* gwh = g_wx_hi + (size_t)layer*64*XK;
        const h16* gwl = g_wx_lo + (size_t)layer*64*XK;
        for (int kc = 0; kc < XK/64; kc++) {
            __syncthreads();
            for (int idx = tid; idx < 512; idx += DINNER) {
                int r = idx >> 3, q = (idx & 7)*8;
                *(uint4*)&Wh[r*72 + q] = *(const uint4*)&gwh[(size_t)r*XK + kc*64 + q];
                *(uint4*)&Wl[r*72 + q] = *(const uint4*)&gwl[(size_t)r*XK + kc*64 + q];
            }
            __syncthreads();
            if (warp < 16) {
#pragma unroll
                for (int ks = 0; ks < 64; ks += 16) {
                    wmma::fragment<wmma::matrix_a,16,16,16,h16,wmma::row_major> ah, al;
                    wmma::fragment<wmma::matrix_b,16,16,16,h16,wmma::col_major> bh, bl;
                    wmma::load_matrix_sync(ah, Ahi + ti*16*XKS + kc*64 + ks, XKS);
                    wmma::load_matrix_sync(al, Alo + ti*16*XKS + kc*64 + ks, XKS);
                    wmma::load_matrix_sync(bh, Wh + tj*16*72 + ks, 72);
                    wmma::load_matrix_sync(bl, Wl + tj*16*72 + ks, 72);
                    wmma::mma_sync(accf, ah, bh, accf);
                    wmma::mma_sync(accf, ah, bl, accf);
                    wmma::mma_sync(accf, al, bh, accf);
                }
            }
        }
        __syncthreads();
        if (warp < 16)
            wmma::store_matrix_sync(sdbl + ti*16*68 + tj*16, accf, 68, wmma::mem_row_major);
    }
    __syncthreads();

    // dbl -> global for scan3
    for (int idx = tid; idx < CHUNK*64; idx += DINNER) {
        int i = idx >> 6, j = idx & 63;
        g_dbl2[(size_t)(m0+i)*NX + j] = sdbl[i*68 + j];
    }

    // ---- scan1 phase ----
    {
        float wreg[DTRANK];
#pragma unroll
        for (int r = 0; r < DTRANK; r++)
            wreg[r] = dt_w[(size_t)(layer*DINNER + d)*DTRANK + r];
        float dbias = dt_b[layer*DINNER + d];
        float A2[DSTATE];
#pragma unroll
        for (int n = 0; n < DSTATE; n++)
            A2[n] = g_A2[(size_t)(layer*DINNER + d)*DSTATE + n];
        float ab = A2[0];
        bool fast = true;
#pragma unroll
        for (int n = 1; n < DSTATE; n++)
            fast = fast && (fabsf(A2[n] - (float)(n+1)*ab)
                            <= 1e-4f*fabsf((float)(n+1)*ab) + 1e-6f);

        float h[DSTATE];
#pragma unroll
        for (int n = 0; n < DSTATE; n++) h[n] = 0.f;
        float sumd = 0.f;

        for (int i = 0; i < CHUNK; i++) {
            float sdt = dbias;
#pragma unroll
            for (int r = 0; r < DTRANK; r++) sdt = fmaf(sdbl[i*68 + r], wreg[r], sdt);
            float delta = softplus_f(sdt);
            float u = __half2float(Ahi[i*XKS + d]) + __half2float(Alo[i*XKS + d]);
            float du = delta * u;
            if (fast) {
                float e1 = ex2(delta * ab);
                float p = e1;
#pragma unroll
                for (int n = 0; n < DSTATE; n++) {
                    h[n] = fmaf(p, h[n], du * sdbl[i*68 + DTRANK + n]);
                    p *= e1;
                }
            } else {
#pragma unroll
                for (int n = 0; n < DSTATE; n++) {
                    float a = ex2(delta * A2[n]);
                    h[n] = fmaf(a, h[n], du * sdbl[i*68 + DTRANK + n]);
                }
            }
            sumd += delta;
        }
        size_t o = ((size_t)(b*NCHUNK + c)*DINNER + d)*DSTATE;
#pragma unroll
        for (int n = 0; n < DSTATE; n++) {
            g_hend[o + n] = h[n];
            g_P[o + n] = ex2(A2[n] * sumd);
        }
    }
}

__global__ void __launch_bounds__(256) scan2_kernel()
{
    int gw = (blockIdx.x*256 + threadIdx.x) >> 5;
    int lane = threadIdx.x & 31;
    if (gw >= BATCH*(DINNER/2)) return;
    int b = gw / (DINNER/2);
    int dp = gw - b*(DINNER/2);
    float H = 0.f;
    for (int c = 0; c < NCHUNK; c++) {
        size_t o = ((size_t)(b*NCHUNK + c)*DINNER + dp*2)*DSTATE + lane;
        float P = g_P[o];
        float E = g_hend[o];
        g_Hin[o] = H;
        H = fmaf(P, H, E);
    }
}

// ---------------- scan3: scan + gate -> yg fp16 (u loaded as half2) ----------------
__global__ void __launch_bounds__(DINNER) scan3_kernel(
    const float* __restrict__ dt_w, const float* __restrict__ dt_b,
    const float* __restrict__ D_param, int layer)
{
    int c = blockIdx.x, b = blockIdx.y;
    int d = threadIdx.x;
    __shared__ float sD[CHUNK][68];
    int t0 = c*CHUNK;
    int m0 = b*TSEQ + t0;
    // coalesced staging: full 64-column padded rows
    for (int idx = d; idx < CHUNK*64; idx += DINNER) {
        int i = idx >> 6, j = idx & 63;
        sD[i][j] = g_dbl2[(size_t)(m0+i)*NX + j];
    }
    float wreg[DTRANK];
#pragma unroll
    for (int r = 0; r < DTRANK; r++)
        wreg[r] = dt_w[(size_t)(layer*DINNER + d)*DTRANK + r];
    float dbias = dt_b[layer*DINNER + d];
    float A2[DSTATE];
#pragma unroll
    for (int n = 0; n < DSTATE; n++)
        A2[n] = g_A2[(size_t)(layer*DINNER + d)*DSTATE + n];
    float ab = A2[0];
    bool fast = true;
#pragma unroll
    for (int n = 1; n < DSTATE; n++)
        fast = fast && (fabsf(A2[n] - (float)(n+1)*ab)
                        <= 1e-4f*fabsf((float)(n+1)*ab) + 1e-6f);

    size_t base = (size_t)(b*TSEQ)*(2*DINNER) + d;
    float h[DSTATE];
    size_t oin = ((size_t)(b*NCHUNK + c)*DINNER + d)*DSTATE;
#pragma unroll
    for (int n = 0; n < DSTATE; n++) h[n] = g_Hin[oin + n];
    float Dp = D_param[layer*DINNER + d];
    __syncthreads();

    for (int i0 = 0; i0 < CHUNK; i0 += 8) {
        __half2 uv[8];
        float zv[8];
#pragma unroll
        for (int j = 0; j < 8; j++) {
            int m = m0 + i0 + j;
            uv[j] = g_u2[(size_t)m*DINNER + d];
            zv[j] = g_xz[base + (size_t)(t0+i0+j)*(2*DINNER) + DINNER];
        }
#pragma unroll
        for (int j = 0; j < 8; j++) {
            int i = i0 + j;
            int m = m0 + i;
            float u = __half2float(__low2half(uv[j])) + __half2float(__high2half(uv[j]));

            float sdt = dbias;
#pragma unroll
            for (int r = 0; r < DTRANK; r++) sdt = fmaf(sD[i][r], wreg[r], sdt);
            float delta = softplus_f(sdt);
            float du = delta * u;
            float y = 0.f;
            if (fast) {
                float e1 = ex2(delta * ab);
                float p = e1;
#pragma unroll
                for (int n = 0; n < DSTATE; n++) {
                    h[n] = fmaf(p, h[n], du * sD[i][DTRANK + n]);
                    y = fmaf(h[n], sD[i][DTRANK + DSTATE + n], y);
                    p *= e1;
                }
            } else {
#pragma unroll
                for (int n = 0; n < DSTATE; n++) {
                    float a = ex2(delta * A2[n]);
                    h[n] = fmaf(a, h[n], du * sD[i][DTRANK + n]);
                    y = fmaf(h[n], sD[i][DTRANK + DSTATE + n], y);
                }
            }
            float silz = silu_f(zv[j]);
            float yg = fmaf(u, Dp, y) * silz;
            g_yg[(size_t)m*DINNER + d] = __float2half_rn(yg);
        }
    }
}

// ---------------- host launcher ----------------
extern "C" void kernel_launch(void* const* d_in, const int* in_sizes, int n_in,
                              void* d_out, int out_size)
{
    (void)in_sizes; (void)n_in; (void)out_size;
    const int*   type_seq = (const int*)  d_in[0];
    const float* time_seq = (const float*)d_in[1];
    const float* temp_seq = (const float*)d_in[2];
    const float* emb      = (const float*)d_in[3];
    const float* norm_w   = (const float*)d_in[4];
    const float* norm_b   = (const float*)d_in[5];
    const float* in_w     = (const float*)d_in[6];
    const float* conv_w   = (const float*)d_in[7];
    const float* conv_b   = (const float*)d_in[8];
    const float* xproj_w  = (const float*)d_in[9];
    const float* dt_w     = (const float*)d_in[10];
    const float* dt_b     = (const float*)d_in[11];
    const float* A_log    = (const float*)d_in[12];
    const float* D_param  = (const float*)d_in[13];
    const float* out_w    = (const float*)d_in[14];
    const float* normf_w  = (const float*)d_in[15];
    const float* normf_b  = (const float*)d_in[16];
    float* out = (float*)d_out;

    float *p_xz, *p_h;
    cudaGetSymbolAddress((void**)&p_xz, g_xz);
    cudaGetSymbolAddress((void**)&p_h,  g_h);
    h16 *p_hn, *p_yg, *p_w1h, *p_w1l, *p_w2h, *p_w2l;
    cudaGetSymbolAddress((void**)&p_hn,  g_hn);
    cudaGetSymbolAddress((void**)&p_yg,  g_yg);
    cudaGetSymbolAddress((void**)&p_w1h, g_w1_hi);
    cudaGetSymbolAddress((void**)&p_w1l, g_w1_lo);
    cudaGetSymbolAddress((void**)&p_w2h, g_w2_hi);
    cudaGetSymbolAddress((void**)&p_w2l, g_w2_lo);

    cudaFuncSetAttribute(gemm_h16,
                         cudaFuncAttributeMaxDynamicSharedMemorySize, GEMM_SMEM);
    cudaFuncSetAttribute(mega1,
                         cudaFuncAttributeMaxDynamicSharedMemorySize, MG_SMEM);

    embed_kernel<<<MROWS, DDIM>>>(type_seq, time_seq, temp_seq, emb);
    prep_all<<<(W1TOT + W2TOT + WXTOT + A2TOT + 255)/256, 256>>>(
        in_w, out_w, xproj_w, A_log);

    for (int l = 0; l < NLAYER; l++) {
        addnorm_kernel<<<MROWS, 128>>>(norm_w + l*DDIM, norm_b + l*DDIM, l > 0);

        gemm_h16<<<dim3((2*DINNER + 127)/128, MROWS/128), 256, GEMM_SMEM>>>(
            p_hn,
            p_w1h + (size_t)l*2*DINNER*KPAD1, p_w1l + (size_t)l*2*DINNER*KPAD1,
            p_xz, MROWS, 2*DINNER, KPAD1);

        mega1<<<dim3(NCHUNK, BATCH), DINNER, MG_SMEM>>>(
            conv_w, conv_b, dt_w, dt_b, l);

        scan2_kernel<<<(BATCH*(DINNER/2)*32 + 255)/256, 256>>>();

        scan3_kernel<<<dim3(NCHUNK, BATCH), DINNER>>>(
            dt_w, dt_b, D_param, l);

        gemm_h16<<<dim3((DDIM + 127)/128, MROWS/128), 256, GEMM_SMEM>>>(
            p_yg,
            p_w2h + (size_t)l*DDIM*DINNER, p_w2l + (size_t)l*DDIM*DINNER,
            p_h, MROWS, DDIM, DINNER);
    }

    final_kernel<<<BATCH*LQ, 128>>>(normf_w, normf_b, out);
}

// round 16
// speedup vs baseline: 1.2752x; 1.0115x over previous
#include <cuda_runtime.h>
#include <cuda_fp16.h>
#include <math.h>
#include <stdint.h>
#include <mma.h>

using namespace nvcuda;

#define BATCH   4
#define LQ      1024
#define TSEQ    2048
#define DMODEL  256
#define DTIME   16
#define DDIM    272
#define KPAD1   288
#define NLAYER  4
#define DINNER  544
#define DSTATE  16
#define DCONV   4
#define DTRANK  17
#define NDBL    (DTRANK + 2*DSTATE)   // 49
#define MROWS   (BATCH*TSEQ)          // 8192
#define NCHUNK  32
#define CHUNK   (TSEQ/NCHUNK)         // 64
#define XK      576
#define XKS     (XK+8)
#define NX      64

typedef __half h16;

__device__ float g_h   [MROWS*DDIM];
__device__ float g_res [MROWS*DDIM];
__device__ float g_xz  [MROWS*2*DINNER];
__device__ float g_dbl2[MROWS*NX];
__device__ float g_hend[BATCH*NCHUNK*DINNER*DSTATE];
__device__ float g_P   [BATCH*NCHUNK*DINNER*DSTATE];
__device__ float g_Hin [BATCH*NCHUNK*DINNER*DSTATE];
__device__ float g_A2  [NLAYER*DINNER*DSTATE];
__device__ __half2 g_u2[MROWS*DINNER];
__device__ h16 g_hn [MROWS*KPAD1];
__device__ h16 g_yg [MROWS*DINNER];
__device__ h16 g_w1_hi[NLAYER*2*DINNER*KPAD1];
__device__ h16 g_w1_lo[NLAYER*2*DINNER*KPAD1];
__device__ h16 g_w2_hi[NLAYER*DDIM*DINNER];
__device__ h16 g_w2_lo[NLAYER*DDIM*DINNER];
__device__ h16 g_wx_hi[NLAYER*64*XK];
__device__ h16 g_wx_lo[NLAYER*64*XK];

__device__ __forceinline__ float ex2(float x) {
    float y; asm("ex2.approx.ftz.f32 %0, %1;" : "=f"(y) : "f"(x)); return y;
}
__device__ __forceinline__ float softplus_f(float x) {
    return fmaxf(x, 0.f) + __logf(1.f + __expf(-fabsf(x)));
}
__device__ __forceinline__ float silu_f(float x) {
    return __fdividef(x, 1.f + __expf(-x));
}
__device__ __forceinline__ void split_h16(float v, h16& hi, h16& lo) {
    hi = __float2half_rn(v);
    lo = __float2half_rn(v - __half2float(hi));
}
__device__ __forceinline__ void cp16(uint32_t saddr, const void* g, int srcsz) {
    asm volatile("cp.async.ca.shared.global [%0], [%1], 16, %2;\n"
                 :: "r"(saddr), "l"(g), "r"(srcsz));
}
__device__ __forceinline__ void cp_commit() { asm volatile("cp.async.commit_group;\n"); }
template<int NN> __device__ __forceinline__ void cp_wait() {
    asm volatile("cp.async.wait_group %0;\n" :: "n"(NN));
}

// ---------------- embedding ----------------
__global__ void __launch_bounds__(DDIM) embed_kernel(
    const int* __restrict__ type_seq, const float* __restrict__ time_seq,
    const float* __restrict__ temp_seq, const float* __restrict__ emb)
{
    int row = blockIdx.x;
    int d = threadIdx.x;
    int b = row / TSEQ, t = row % TSEQ;
    float v;
    if (t < LQ) {
        if (d < DMODEL) {
            v = tanhf(emb[(size_t)type_seq[b*LQ + t]*DMODEL + d]);
        } else {
            int j = d - DMODEL;
            int i = j >> 1;
            float div = expf(-0.57564627324851142f * (float)(2*i));
            float arg = time_seq[b*LQ + t] * div;
            v = (j & 1) ? cosf(arg) : sinf(arg);
        }
    } else {
        v = (d < DMODEL) ? 0.f
                         : temp_seq[(size_t)(b*LQ + (t - LQ))*DTIME + (d - DMODEL)];
    }
    g_h[(size_t)row*DDIM + d] = v;
}

// ---------------- one-time prep ----------------
#define W1TOT (NLAYER*2*DINNER*KPAD1)
#define W2TOT (NLAYER*DDIM*DINNER)
#define WXTOT (NLAYER*64*XK)
#define A2TOT (NLAYER*DINNER*DSTATE)
__global__ void __launch_bounds__(256) prep_all(
    const float* __restrict__ in_w, const float* __restrict__ out_w,
    const float* __restrict__ xproj_w, const float* __restrict__ A_log)
{
    int idx = blockIdx.x*256 + threadIdx.x;
    if (idx < W1TOT) {
        const int per = 2*DINNER*KPAD1;
        int l = idx / per, rem = idx - l*per;
        int r = rem / KPAD1, c = rem - r*KPAD1;
        float v = (c < DDIM) ? in_w[((size_t)l*2*DINNER + r)*DDIM + c] : 0.f;
        split_h16(v, g_w1_hi[idx], g_w1_lo[idx]);
    } else if (idx < W1TOT + W2TOT) {
        int j = idx - W1TOT;
        split_h16(out_w[j], g_w2_hi[j], g_w2_lo[j]);
    } else if (idx < W1TOT + W2TOT + WXTOT) {
        int j = idx - W1TOT - W2TOT;
        const int per = 64*XK;
        int l = j / per, rem = j - l*per;
        int r = rem / XK, cc = rem - r*XK;
        float v = (r < NDBL && cc < DINNER)
                ? xproj_w[((size_t)l*NDBL + r)*DINNER + cc] : 0.f;
        split_h16(v, g_wx_hi[j], g_wx_lo[j]);
    } else if (idx < W1TOT + W2TOT + WXTOT + A2TOT) {
        int j = idx - W1TOT - W2TOT - WXTOT;
        g_A2[j] = -__expf(A_log[j]) * 1.4426950408889634f;
    }
}

// ---------------- warp-per-row residual add + layernorm -> fp16 hn ----------------
__global__ void __launch_bounds__(256) addnorm_kernel(
    const float* __restrict__ gamma, const float* __restrict__ beta, int addflag)
{
    int row = blockIdx.x*8 + (threadIdx.x >> 5);
    int lane = threadIdx.x & 31;
    float v[9];
    float s = 0.f, s2 = 0.f;
    size_t ro = (size_t)row*DDIM;
#pragma unroll
    for (int j = 0; j < 9; j++) {
        int d = lane + j*32;
        float x = 0.f;
        if (d < DDIM) {
            x = g_h[ro + d];
            if (addflag) x += g_res[ro + d];
        }
        v[j] = x; s += x; s2 += x*x;
    }
#pragma unroll
    for (int o = 16; o > 0; o >>= 1) {
        s  += __shfl_xor_sync(0xffffffffu, s,  o);
        s2 += __shfl_xor_sync(0xffffffffu, s2, o);
    }
    float mean = s * (1.f/DDIM);
    float var  = s2 * (1.f/DDIM) - mean*mean;
    float rstd = rsqrtf(var + 1e-5f);
    size_t ho = (size_t)row*KPAD1;
#pragma unroll
    for (int j = 0; j < 9; j++) {
        int d = lane + j*32;
        if (d < DDIM) {
            g_res[ro + d] = v[j];
            float hn = (v[j]-mean)*rstd*gamma[d] + beta[d];
            g_hn[ho + d] = __float2half_rn(hn);
        } else if (d < KPAD1) {
            g_hn[ho + d] = __float2half(0.f);
        }
    }
}

// ---------------- warp-per-row final add + layernorm ----------------
__global__ void __launch_bounds__(256) final_kernel(
    const float* __restrict__ gamma, const float* __restrict__ beta,
    float* __restrict__ out)
{
    int rowo = blockIdx.x*8 + (threadIdx.x >> 5);
    int lane = threadIdx.x & 31;
    int b = rowo / LQ, t = rowo % LQ;
    size_t mo = (size_t)(b*TSEQ + t)*DDIM;
    float v[9];
    float s = 0.f, s2 = 0.f;
#pragma unroll
    for (int j = 0; j < 9; j++) {
        int d = lane + j*32;
        float x = 0.f;
        if (d < DDIM) x = g_h[mo + d] + g_res[mo + d];
        v[j] = x; s += x; s2 += x*x;
    }
#pragma unroll
    for (int o = 16; o > 0; o >>= 1) {
        s  += __shfl_xor_sync(0xffffffffu, s,  o);
        s2 += __shfl_xor_sync(0xffffffffu, s2, o);
    }
    float mean = s * (1.f/DDIM);
    float var  = s2 * (1.f/DDIM) - mean*mean;
    float rstd = rsqrtf(var + 1e-5f);
    size_t oo = (size_t)rowo*DDIM;
#pragma unroll
    for (int j = 0; j < 9; j++) {
        int d = lane + j*32;
        if (d < DDIM)
            out[oo + d] = (v[j]-mean)*rstd*gamma[d] + beta[d];
    }
}

// ---------------- fp16 2-term GEMM, cp.async 2-stage + slab skip ----------------
#define SPAD 8
#define SROW (32+SPAD)
__global__ void __launch_bounds__(256, 2) gemm_h16(
    const h16* __restrict__ A,
    const h16* __restrict__ Whi, const h16* __restrict__ Wlo,
    float* __restrict__ C, int M, int N, int Kpad)
{
    extern __shared__ h16 sm[];
    int tid = threadIdx.x;
    int warp = tid >> 5;
    int wm = warp >> 2;
    int wn = warp & 3;
    int mb = blockIdx.y * 128;
    int nb = blockIdx.x * 128;
    bool wnvalid = (nb + wn*32) < N;

    int aIdx0 = tid*2, aIdx1 = tid*2 + 1;
    int r0 = aIdx0 >> 2, c0 = (aIdx0 & 3) * 8;
    int r1 = aIdx1 >> 2, c1 = (aIdx1 & 3) * 8;
    int wsz0 = ((nb + r0) < N) ? 16 : 0;
    int wsz1 = ((nb + r1) < N) ? 16 : 0;

    const h16* pA0 = A   + (size_t)(mb + r0)*Kpad + c0;
    const h16* pA1 = A   + (size_t)(mb + r1)*Kpad + c1;
    const h16* pW0 = Whi + (size_t)(nb + r0)*Kpad + c0;
    const h16* pW1 = Whi + (size_t)(nb + r1)*Kpad + c1;
    const h16* pV0 = Wlo + (size_t)(nb + r0)*Kpad + c0;
    const h16* pV1 = Wlo + (size_t)(nb + r1)*Kpad + c1;

    uint32_t sbase = (uint32_t)__cvta_generic_to_shared(sm);
    auto soff = [&](int stage, int arr, int row, int col) -> uint32_t {
        return (uint32_t)((((stage*3 + arr)*128) + row)*SROW + col);
    };
    uint32_t dA0 = soff(0,0,r0,c0), dA1 = soff(0,0,r1,c1);
    uint32_t dW0 = soff(0,1,r0,c0), dW1 = soff(0,1,r1,c1);
    uint32_t dV0 = soff(0,2,r0,c0), dV1 = soff(0,2,r1,c1);
    const uint32_t STG = 3*128*SROW;

    wmma::fragment<wmma::accumulator,16,16,16,float> acc[4][2];
#pragma unroll
    for (int i = 0; i < 4; i++)
#pragma unroll
        for (int j = 0; j < 2; j++) wmma::fill_fragment(acc[i][j], 0.f);

    int ktiles = Kpad >> 5;

    cp16(sbase + 2*dA0, pA0, 16); cp16(sbase + 2*dA1, pA1, 16);
    cp16(sbase + 2*dW0, pW0, wsz0); cp16(sbase + 2*dW1, pW1, wsz1);
    cp16(sbase + 2*dV0, pV0, wsz0); cp16(sbase + 2*dV1, pV1, wsz1);
    cp_commit();

    for (int kt = 0; kt < ktiles; kt++) {
        if (kt + 1 < ktiles) {
            int st = (kt+1) & 1;
            int go = (kt+1) * 32;
            uint32_t so = st * STG;
            cp16(sbase + 2*(dA0+so), pA0 + go, 16); cp16(sbase + 2*(dA1+so), pA1 + go, 16);
            cp16(sbase + 2*(dW0+so), pW0 + go, wsz0); cp16(sbase + 2*(dW1+so), pW1 + go, wsz1);
            cp16(sbase + 2*(dV0+so), pV0 + go, wsz0); cp16(sbase + 2*(dV1+so), pV1 + go, wsz1);
            cp_commit();
            cp_wait<1>();
        } else {
            cp_wait<0>();
        }
        __syncthreads();

        if (wnvalid) {
            const h16* bA   = sm + (size_t)(kt&1)*STG + 0*128*SROW;
            const h16* bWhi = sm + (size_t)(kt&1)*STG + 1*128*SROW;
            const h16* bWlo = sm + (size_t)(kt&1)*STG + 2*128*SROW;
#pragma unroll
            for (int ks = 0; ks < 32; ks += 16) {
                wmma::fragment<wmma::matrix_b,16,16,16,h16,wmma::col_major> bhi[2], blo[2];
#pragma unroll
                for (int j = 0; j < 2; j++) {
                    wmma::load_matrix_sync(bhi[j], bWhi + (wn*32 + j*16)*SROW + ks, SROW);
                    wmma::load_matrix_sync(blo[j], bWlo + (wn*32 + j*16)*SROW + ks, SROW);
                }
#pragma unroll
                for (int i = 0; i < 4; i++) {
                    wmma::fragment<wmma::matrix_a,16,16,16,h16,wmma::row_major> af;
                    wmma::load_matrix_sync(af, bA + (wm*64 + i*16)*SROW + ks, SROW);
#pragma unroll
                    for (int j = 0; j < 2; j++) {
                        wmma::mma_sync(acc[i][j], af, bhi[j], acc[i][j]);
                        wmma::mma_sync(acc[i][j], af, blo[j], acc[i][j]);
                    }
                }
            }
        }
        __syncthreads();
    }
    if (wnvalid) {
#pragma unroll
        for (int i = 0; i < 4; i++)
#pragma unroll
            for (int j = 0; j < 2; j++) {
                int n0 = nb + wn*32 + j*16;
                if (n0 < N)
                    wmma::store_matrix_sync(C + (size_t)(mb + wm*64 + i*16)*N + n0,
                                            acc[i][j], N, wmma::mem_row_major);
            }
    }
}
#define GEMM_SMEM (2*3*128*SROW*2)   // 61440 bytes

// ---------------- mega1: conv + x_proj (3-term fp16 tensor) + scan1 ----------------
#define MG_AHI  0
#define MG_ALO  (CHUNK*XKS*2)
#define MG_WH   (2*CHUNK*XKS*2)
#define MG_WL   (MG_WH + 64*72*2)
#define MG_DBL  (MG_WL + 64*72*2)
#define MG_SMEM (MG_DBL + CHUNK*68*4)
__global__ void __launch_bounds__(DINNER) mega1(
    const float* __restrict__ conv_w, const float* __restrict__ conv_b,
    const float* __restrict__ dt_w, const float* __restrict__ dt_b,
    int layer)
{
    extern __shared__ __align__(16) char smx[];
    h16*  Ahi  = (h16*)(smx + MG_AHI);
    h16*  Alo  = (h16*)(smx + MG_ALO);
    h16*  Wh   = (h16*)(smx + MG_WH);
    h16*  Wl   = (h16*)(smx + MG_WL);
    float* sdbl = (float*)(smx + MG_DBL);

    int c = blockIdx.x, b = blockIdx.y;
    int tid = threadIdx.x;
    int d = tid;
    int warp = tid >> 5;
    int t0 = c*CHUNK;
    int m0 = b*TSEQ + t0;

    // ---- conv phase (MLP-batched loads); also export u split to global ----
    {
        const float* wp = conv_w + (size_t)(layer*DINNER + d)*DCONV;
        float w0 = wp[0], w1 = wp[1], w2 = wp[2], w3 = wp[3];
        float bias = conv_b[layer*DINNER + d];
        size_t base = (size_t)(b*TSEQ)*(2*DINNER) + d;
        float x0 = (t0-3 >= 0) ? g_xz[base + (size_t)(t0-3)*(2*DINNER)] : 0.f;
        float x1 = (t0-2 >= 0) ? g_xz[base + (size_t)(t0-2)*(2*DINNER)] : 0.f;
        float x2 = (t0-1 >= 0) ? g_xz[base + (size_t)(t0-1)*(2*DINNER)] : 0.f;
        for (int i0 = 0; i0 < CHUNK; i0 += 8) {
            float xv[8];
#pragma unroll
            for (int j = 0; j < 8; j++)
                xv[j] = g_xz[base + (size_t)(t0+i0+j)*(2*DINNER)];
#pragma unroll
            for (int j = 0; j < 8; j++) {
                float x3 = xv[j];
                float s = bias;
                s = fmaf(w0, x0, s); s = fmaf(w1, x1, s);
                s = fmaf(w2, x2, s); s = fmaf(w3, x3, s);
                float sl = silu_f(s);
                h16 hi, lo; split_h16(sl, hi, lo);
                Ahi[(i0+j)*XKS + d] = hi;
                Alo[(i0+j)*XKS + d] = lo;
                g_u2[(size_t)(m0+i0+j)*DINNER + d] = __halves2half2(hi, lo);
                x0 = x1; x1 = x2; x2 = x3;
            }
        }
        if (d < XK - DINNER) {
            h16 z0 = __float2half(0.f);
            for (int i = 0; i < CHUNK; i++) {
                Ahi[i*XKS + DINNER + d] = z0;
                Alo[i*XKS + DINNER + d] = z0;
            }
        }
    }
    __syncthreads();

    // ---- x_proj GEMM: sdbl[64][64] = A[64][576] @ Wx[64][576]^T (3-term) ----
    {
        wmma::fragment<wmma::accumulator,16,16,16,float> accf;
        if (warp < 16) wmma::fill_fragment(accf, 0.f);
        int ti = warp >> 2, tj = warp & 3;
        const h16* gwh = g_wx_hi + (size_t)layer*64*XK;
        const h16* gwl = g_wx_lo + (size_t)layer*64*XK;
        for (int kc = 0; kc < XK/64; kc++) {
            __syncthreads();
            for (int idx = tid; idx < 512; idx += DINNER) {
                int r = idx >> 3, q = (idx & 7)*8;
                *(uint4*)&Wh[r*72 + q] = *(const uint4*)&gwh[(size_t)r*XK + kc*64 + q];
                *(uint4*)&Wl[r*72 + q] = *(const uint4*)&gwl[(size_t)r*XK + kc*64 + q];
            }
            __syncthreads();
            if (warp < 16) {
#pragma unroll
                for (int ks = 0; ks < 64; ks += 16) {
                    wmma::fragment<wmma::matrix_a,16,16,16,h16,wmma::row_major> ah, al;
                    wmma::fragment<wmma::matrix_b,16,16,16,h16,wmma::col_major> bh, bl;
                    wmma::load_matrix_sync(ah, Ahi + ti*16*XKS + kc*64 + ks, XKS);
                    wmma::load_matrix_sync(al, Alo + ti*16*XKS + kc*64 + ks, XKS);
                    wmma::load_matrix_sync(bh, Wh + tj*16*72 + ks, 72);
                    wmma::load_matrix_sync(bl, Wl + tj*16*72 + ks, 72);
                    wmma::mma_sync(accf, ah, bh, accf);
                    wmma::mma_sync(accf, ah, bl, accf);
                    wmma::mma_sync(accf, al, bh, accf);
                }
            }
        }
        __syncthreads();
        if (warp < 16)
            wmma::store_matrix_sync(sdbl + ti*16*68 + tj*16, accf, 68, wmma::mem_row_major);
    }
    __syncthreads();

    // dbl -> global for scan3
    for (int idx = tid; idx < CHUNK*64; idx += DINNER) {
        int i = idx >> 6, j = idx & 63;
        g_dbl2[(size_t)(m0+i)*NX + j] = sdbl[i*68 + j];
    }

    // ---- scan1 phase ----
    {
        float wreg[DTRANK];
#pragma unroll
        for (int r = 0; r < DTRANK; r++)
            wreg[r] = dt_w[(size_t)(layer*DINNER + d)*DTRANK + r];
        float dbias = dt_b[layer*DINNER + d];
        float A2[DSTATE];
#pragma unroll
        for (int n = 0; n < DSTATE; n++)
            A2[n] = g_A2[(size_t)(layer*DINNER + d)*DSTATE + n];
        float ab = A2[0];
        bool fast = true;
#pragma unroll
        for (int n = 1; n < DSTATE; n++)
            fast = fast && (fabsf(A2[n] - (float)(n+1)*ab)
                            <= 1e-4f*fabsf((float)(n+1)*ab) + 1e-6f);

        float h[DSTATE];
#pragma unroll
        for (int n = 0; n < DSTATE; n++) h[n] = 0.f;
        float sumd = 0.f;

        for (int i = 0; i < CHUNK; i++) {
            float sdt = dbias;
#pragma unroll
            for (int r = 0; r < DTRANK; r++) sdt = fmaf(sdbl[i*68 + r], wreg[r], sdt);
            float delta = softplus_f(sdt);
            float u = __half2float(Ahi[i*XKS + d]) + __half2float(Alo[i*XKS + d]);
            float du = delta * u;
            if (fast) {
                float e1 = ex2(delta * ab);
                float p = e1;
#pragma unroll
                for (int n = 0; n < DSTATE; n++) {
                    h[n] = fmaf(p, h[n], du * sdbl[i*68 + DTRANK + n]);
                    p *= e1;
                }
            } else {
#pragma unroll
                for (int n = 0; n < DSTATE; n++) {
                    float a = ex2(delta * A2[n]);
                    h[n] = fmaf(a, h[n], du * sdbl[i*68 + DTRANK + n]);
                }
            }
            sumd += delta;
        }
        size_t o = ((size_t)(b*NCHUNK + c)*DINNER + d)*DSTATE;
#pragma unroll
        for (int n = 0; n < DSTATE; n++) {
            g_hend[o + n] = h[n];
            g_P[o + n] = ex2(A2[n] * sumd);
        }
    }
}

__global__ void __launch_bounds__(256) scan2_kernel()
{
    int gw = (blockIdx.x*256 + threadIdx.x) >> 5;
    int lane = threadIdx.x & 31;
    if (gw >= BATCH*(DINNER/2)) return;
    int b = gw / (DINNER/2);
    int dp = gw - b*(DINNER/2);
    float H = 0.f;
    for (int c = 0; c < NCHUNK; c++) {
        size_t o = ((size_t)(b*NCHUNK + c)*DINNER + dp*2)*DSTATE + lane;
        float P = g_P[o];
        float E = g_hend[o];
        g_Hin[o] = H;
        H = fmaf(P, H, E);
    }
}

// ---------------- scan3: scan + gate -> yg fp16 ----------------
__global__ void __launch_bounds__(DINNER) scan3_kernel(
    const float* __restrict__ dt_w, const float* __restrict__ dt_b,
    const float* __restrict__ D_param, int layer)
{
    int c = blockIdx.x, b = blockIdx.y;
    int d = threadIdx.x;
    __shared__ float sD[CHUNK][68];
    int t0 = c*CHUNK;
    int m0 = b*TSEQ + t0;
    for (int idx = d; idx < CHUNK*64; idx += DINNER) {
        int i = idx >> 6, j = idx & 63;
        sD[i][j] = g_dbl2[(size_t)(m0+i)*NX + j];
    }
    float wreg[DTRANK];
#pragma unroll
    for (int r = 0; r < DTRANK; r++)
        wreg[r] = dt_w[(size_t)(layer*DINNER + d)*DTRANK + r];
    float dbias = dt_b[layer*DINNER + d];
    float A2[DSTATE];
#pragma unroll
    for (int n = 0; n < DSTATE; n++)
        A2[n] = g_A2[(size_t)(layer*DINNER + d)*DSTATE + n];
    float ab = A2[0];
    bool fast = true;
#pragma unroll
    for (int n = 1; n < DSTATE; n++)
        fast = fast && (fabsf(A2[n] - (float)(n+1)*ab)
                        <= 1e-4f*fabsf((float)(n+1)*ab) + 1e-6f);

    size_t base = (size_t)(b*TSEQ)*(2*DINNER) + d;
    float h[DSTATE];
    size_t oin = ((size_t)(b*NCHUNK + c)*DINNER + d)*DSTATE;
#pragma unroll
    for (int n = 0; n < DSTATE; n++) h[n] = g_Hin[oin + n];
    float Dp = D_param[layer*DINNER + d];
    __syncthreads();

    for (int i0 = 0; i0 < CHUNK; i0 += 8) {
        __half2 uv[8];
        float zv[8];
#pragma unroll
        for (int j = 0; j < 8; j++) {
            int m = m0 + i0 + j;
            uv[j] = g_u2[(size_t)m*DINNER + d];
            zv[j] = g_xz[base + (size_t)(t0+i0+j)*(2*DINNER) + DINNER];
        }
#pragma unroll
        for (int j = 0; j < 8; j++) {
            int i = i0 + j;
            int m = m0 + i;
            float u = __half2float(__low2half(uv[j])) + __half2float(__high2half(uv[j]));

            float sdt = dbias;
#pragma unroll
            for (int r = 0; r < DTRANK; r++) sdt = fmaf(sD[i][r], wreg[r], sdt);
            float delta = softplus_f(sdt);
            float du = delta * u;
            float y = 0.f;
            if (fast) {
                float e1 = ex2(delta * ab);
                float p = e1;
#pragma unroll
                for (int n = 0; n < DSTATE; n++) {
                    h[n] = fmaf(p, h[n], du * sD[i][DTRANK + n]);
                    y = fmaf(h[n], sD[i][DTRANK + DSTATE + n], y);
                    p *= e1;
                }
            } else {
#pragma unroll
                for (int n = 0; n < DSTATE; n++) {
                    float a = ex2(delta * A2[n]);
                    h[n] = fmaf(a, h[n], du * sD[i][DTRANK + n]);
                    y = fmaf(h[n], sD[i][DTRANK + DSTATE + n], y);
                }
            }
            float silz = silu_f(zv[j]);
            float yg = fmaf(u, Dp, y) * silz;
            g_yg[(size_t)m*DINNER + d] = __float2half_rn(yg);
        }
    }
}

// ---------------- host launcher ----------------
extern "C" void kernel_launch(void* const* d_in, const int* in_sizes, int n_in,
                              void* d_out, int out_size)
{
    (void)in_sizes; (void)n_in; (void)out_size;
    const int*   type_seq = (const int*)  d_in[0];
    const float* time_seq = (const float*)d_in[1];
    const float* temp_seq = (const float*)d_in[2];
    const float* emb      = (const float*)d_in[3];
    const float* norm_w   = (const float*)d_in[4];
    const float* norm_b   = (const float*)d_in[5];
    const float* in_w     = (const float*)d_in[6];
    const float* conv_w   = (const float*)d_in[7];
    const float* conv_b   = (const float*)d_in[8];
    const float* xproj_w  = (const float*)d_in[9];
    const float* dt_w     = (const float*)d_in[10];
    const float* dt_b     = (const float*)d_in[11];
    const float* A_log    = (const float*)d_in[12];
    const float* D_param  = (const float*)d_in[13];
    const float* out_w    = (const float*)d_in[14];
    const float* normf_w  = (const float*)d_in[15];
    const float* normf_b  = (const float*)d_in[16];
    float* out = (float*)d_out;

    float *p_xz, *p_h;
    cudaGetSymbolAddress((void**)&p_xz, g_xz);
    cudaGetSymbolAddress((void**)&p_h,  g_h);
    h16 *p_hn, *p_yg, *p_w1h, *p_w1l, *p_w2h, *p_w2l;
    cudaGetSymbolAddress((void**)&p_hn,  g_hn);
    cudaGetSymbolAddress((void**)&p_yg,  g_yg);
    cudaGetSymbolAddress((void**)&p_w1h, g_w1_hi);
    cudaGetSymbolAddress((void**)&p_w1l, g_w1_lo);
    cudaGetSymbolAddress((void**)&p_w2h, g_w2_hi);
    cudaGetSymbolAddress((void**)&p_w2l, g_w2_lo);

    cudaFuncSetAttribute(gemm_h16,
                         cudaFuncAttributeMaxDynamicSharedMemorySize, GEMM_SMEM);
    cudaFuncSetAttribute(mega1,
                         cudaFuncAttributeMaxDynamicSharedMemorySize, MG_SMEM);

    embed_kernel<<<MROWS, DDIM>>>(type_seq, time_seq, temp_seq, emb);
    prep_all<<<(W1TOT + W2TOT + WXTOT + A2TOT + 255)/256, 256>>>(
        in_w, out_w, xproj_w, A_log);

    for (int l = 0; l < NLAYER; l++) {
        addnorm_kernel<<<MROWS/8, 256>>>(norm_w + l*DDIM, norm_b + l*DDIM, l > 0);

        gemm_h16<<<dim3((2*DINNER + 127)/128, MROWS/128), 256, GEMM_SMEM>>>(
            p_hn,
            p_w1h + (size_t)l*2*DINNER*KPAD1, p_w1l + (size_t)l*2*DINNER*KPAD1,
            p_xz, MROWS, 2*DINNER, KPAD1);

        mega1<<<dim3(NCHUNK, BATCH), DINNER, MG_SMEM>>>(
            conv_w, conv_b, dt_w, dt_b, l);

        scan2_kernel<<<(BATCH*(DINNER/2)*32 + 255)/256, 256>>>();

        scan3_kernel<<<dim3(NCHUNK, BATCH), DINNER>>>(
            dt_w, dt_b, D_param, l);

        gemm_h16<<<dim3((DDIM + 127)/128, MROWS/128), 256, GEMM_SMEM>>>(
            p_yg,
            p_w2h + (size_t)l*DDIM*DINNER, p_w2l + (size_t)l*DDIM*DINNER,
            p_h, MROWS, DDIM, DINNER);
    }

    final_kernel<<<(BATCH*LQ)/8, 256>>>(normf_w, normf_b, out);
}

// round 17
// speedup vs baseline: 1.3298x; 1.0428x over previous
#include <cuda_runtime.h>
#include <cuda_fp16.h>
#include <math.h>
#include <stdint.h>
#include <mma.h>

using namespace nvcuda;

#define BATCH   4
#define LQ      1024
#define TSEQ    2048
#define DMODEL  256
#define DTIME   16
#define DDIM    272
#define KPAD1   288
#define NLAYER  4
#define DINNER  544
#define DSTATE  16
#define DCONV   4
#define DTRANK  17
#define NDBL    (DTRANK + 2*DSTATE)   // 49
#define MROWS   (BATCH*TSEQ)          // 8192
#define NCHUNK  32
#define CHUNK   (TSEQ/NCHUNK)         // 64
#define XK      576
#define XKS     (XK+8)
#define NBLK    (NCHUNK*BATCH)        // 128 persistent blocks

typedef __half h16;

__device__ float g_h   [MROWS*DDIM];
__device__ float g_res [MROWS*DDIM];
__device__ float g_xz  [MROWS*2*DINNER];
__device__ float g_hend[BATCH*NCHUNK*DINNER*DSTATE];
__device__ float g_P   [BATCH*NCHUNK*DINNER*DSTATE];
__device__ float g_Hin [BATCH*NCHUNK*DINNER*DSTATE];
__device__ float g_A2  [NLAYER*DINNER*DSTATE];
__device__ h16 g_hn [MROWS*KPAD1];
__device__ h16 g_yg [MROWS*DINNER];
__device__ h16 g_w1_hi[NLAYER*2*DINNER*KPAD1];
__device__ h16 g_w1_lo[NLAYER*2*DINNER*KPAD1];
__device__ h16 g_w2_hi[NLAYER*DDIM*DINNER];
__device__ h16 g_w2_lo[NLAYER*DDIM*DINNER];
__device__ h16 g_wx_hi[NLAYER*64*XK];
__device__ h16 g_wx_lo[NLAYER*64*XK];
// software grid barrier state (returns to neutral after each full barrier)
__device__ unsigned g_bar_cnt = 0;
__device__ volatile unsigned g_bar_gen = 0;

__device__ __forceinline__ float ex2(float x) {
    float y; asm("ex2.approx.ftz.f32 %0, %1;" : "=f"(y) : "f"(x)); return y;
}
__device__ __forceinline__ float softplus_f(float x) {
    return fmaxf(x, 0.f) + __logf(1.f + __expf(-fabsf(x)));
}
__device__ __forceinline__ float silu_f(float x) {
    return __fdividef(x, 1.f + __expf(-x));
}
__device__ __forceinline__ void split_h16(float v, h16& hi, h16& lo) {
    hi = __float2half_rn(v);
    lo = __float2half_rn(v - __half2float(hi));
}
__device__ __forceinline__ void cp16(uint32_t saddr, const void* g, int srcsz) {
    asm volatile("cp.async.ca.shared.global [%0], [%1], 16, %2;\n"
                 :: "r"(saddr), "l"(g), "r"(srcsz));
}
__device__ __forceinline__ void cp_commit() { asm volatile("cp.async.commit_group;\n"); }
template<int NN> __device__ __forceinline__ void cp_wait() {
    asm volatile("cp.async.wait_group %0;\n" :: "n"(NN));
}
// sense-reversing global barrier; all NBLK blocks co-resident (1 CTA/SM, 128<=148)
__device__ __forceinline__ void gridbar() {
    __syncthreads();
    if (threadIdx.x == 0) {
        __threadfence();
        unsigned gen = g_bar_gen;
        if (atomicAdd(&g_bar_cnt, 1u) == NBLK - 1u) {
            g_bar_cnt = 0;
            __threadfence();
            g_bar_gen = gen + 1u;
        } else {
            while (g_bar_gen == gen) __nanosleep(64);
            __threadfence();
        }
    }
    __syncthreads();
}

// ---------------- embedding ----------------
__global__ void __launch_bounds__(DDIM) embed_kernel(
    const int* __restrict__ type_seq, const float* __restrict__ time_seq,
    const float* __restrict__ temp_seq, const float* __restrict__ emb)
{
    int row = blockIdx.x;
    int d = threadIdx.x;
    int b = row / TSEQ, t = row % TSEQ;
    float v;
    if (t < LQ) {
        if (d < DMODEL) {
            v = tanhf(emb[(size_t)type_seq[b*LQ + t]*DMODEL + d]);
        } else {
            int j = d - DMODEL;
            int i = j >> 1;
            float div = expf(-0.57564627324851142f * (float)(2*i));
            float arg = time_seq[b*LQ + t] * div;
            v = (j & 1) ? cosf(arg) : sinf(arg);
        }
    } else {
        v = (d < DMODEL) ? 0.f
                         : temp_seq[(size_t)(b*LQ + (t - LQ))*DTIME + (d - DMODEL)];
    }
    g_h[(size_t)row*DDIM + d] = v;
}

// ---------------- one-time prep ----------------
#define W1TOT (NLAYER*2*DINNER*KPAD1)
#define W2TOT (NLAYER*DDIM*DINNER)
#define WXTOT (NLAYER*64*XK)
#define A2TOT (NLAYER*DINNER*DSTATE)
__global__ void __launch_bounds__(256) prep_all(
    const float* __restrict__ in_w, const float* __restrict__ out_w,
    const float* __restrict__ xproj_w, const float* __restrict__ A_log)
{
    int idx = blockIdx.x*256 + threadIdx.x;
    if (idx < W1TOT) {
        const int per = 2*DINNER*KPAD1;
        int l = idx / per, rem = idx - l*per;
        int r = rem / KPAD1, c = rem - r*KPAD1;
        float v = (c < DDIM) ? in_w[((size_t)l*2*DINNER + r)*DDIM + c] : 0.f;
        split_h16(v, g_w1_hi[idx], g_w1_lo[idx]);
    } else if (idx < W1TOT + W2TOT) {
        int j = idx - W1TOT;
        split_h16(out_w[j], g_w2_hi[j], g_w2_lo[j]);
    } else if (idx < W1TOT + W2TOT + WXTOT) {
        int j = idx - W1TOT - W2TOT;
        const int per = 64*XK;
        int l = j / per, rem = j - l*per;
        int r = rem / XK, cc = rem - r*XK;
        float v = (r < NDBL && cc < DINNER)
                ? xproj_w[((size_t)l*NDBL + r)*DINNER + cc] : 0.f;
        split_h16(v, g_wx_hi[j], g_wx_lo[j]);
    } else if (idx < W1TOT + W2TOT + WXTOT + A2TOT) {
        int j = idx - W1TOT - W2TOT - WXTOT;
        g_A2[j] = -__expf(A_log[j]) * 1.4426950408889634f;
    }
}

// ---------------- warp-per-row residual add + layernorm -> fp16 hn ----------------
__global__ void __launch_bounds__(256) addnorm_kernel(
    const float* __restrict__ gamma, const float* __restrict__ beta, int addflag)
{
    int row = blockIdx.x*8 + (threadIdx.x >> 5);
    int lane = threadIdx.x & 31;
    float v[9];
    float s = 0.f, s2 = 0.f;
    size_t ro = (size_t)row*DDIM;
#pragma unroll
    for (int j = 0; j < 9; j++) {
        int d = lane + j*32;
        float x = 0.f;
        if (d < DDIM) {
            x = g_h[ro + d];
            if (addflag) x += g_res[ro + d];
        }
        v[j] = x; s += x; s2 += x*x;
    }
#pragma unroll
    for (int o = 16; o > 0; o >>= 1) {
        s  += __shfl_xor_sync(0xffffffffu, s,  o);
        s2 += __shfl_xor_sync(0xffffffffu, s2, o);
    }
    float mean = s * (1.f/DDIM);
    float var  = s2 * (1.f/DDIM) - mean*mean;
    float rstd = rsqrtf(var + 1e-5f);
    size_t ho = (size_t)row*KPAD1;
#pragma unroll
    for (int j = 0; j < 9; j++) {
        int d = lane + j*32;
        if (d < DDIM) {
            g_res[ro + d] = v[j];
            float hn = (v[j]-mean)*rstd*gamma[d] + beta[d];
            g_hn[ho + d] = __float2half_rn(hn);
        } else if (d < KPAD1) {
            g_hn[ho + d] = __float2half(0.f);
        }
    }
}

// ---------------- warp-per-row final add + layernorm ----------------
__global__ void __launch_bounds__(256) final_kernel(
    const float* __restrict__ gamma, const float* __restrict__ beta,
    float* __restrict__ out)
{
    int rowo = blockIdx.x*8 + (threadIdx.x >> 5);
    int lane = threadIdx.x & 31;
    int b = rowo / LQ, t = rowo % LQ;
    size_t mo = (size_t)(b*TSEQ + t)*DDIM;
    float v[9];
    float s = 0.f, s2 = 0.f;
#pragma unroll
    for (int j = 0; j < 9; j++) {
        int d = lane + j*32;
        float x = 0.f;
        if (d < DDIM) x = g_h[mo + d] + g_res[mo + d];
        v[j] = x; s += x; s2 += x*x;
    }
#pragma unroll
    for (int o = 16; o > 0; o >>= 1) {
        s  += __shfl_xor_sync(0xffffffffu, s,  o);
        s2 += __shfl_xor_sync(0xffffffffu, s2, o);
    }
    float mean = s * (1.f/DDIM);
    float var  = s2 * (1.f/DDIM) - mean*mean;
    float rstd = rsqrtf(var + 1e-5f);
    size_t oo = (size_t)rowo*DDIM;
#pragma unroll
    for (int j = 0; j < 9; j++) {
        int d = lane + j*32;
        if (d < DDIM)
            out[oo + d] = (v[j]-mean)*rstd*gamma[d] + beta[d];
    }
}

// ---------------- fp16 2-term GEMM, cp.async 2-stage + slab skip ----------------
#define SPAD 8
#define SROW (32+SPAD)
__global__ void __launch_bounds__(256, 2) gemm_h16(
    const h16* __restrict__ A,
    const h16* __restrict__ Whi, const h16* __restrict__ Wlo,
    float* __restrict__ C, int M, int N, int Kpad)
{
    extern __shared__ h16 sm[];
    int tid = threadIdx.x;
    int warp = tid >> 5;
    int wm = warp >> 2;
    int wn = warp & 3;
    int mb = blockIdx.y * 128;
    int nb = blockIdx.x * 128;
    bool wnvalid = (nb + wn*32) < N;

    int aIdx0 = tid*2, aIdx1 = tid*2 + 1;
    int r0 = aIdx0 >> 2, c0 = (aIdx0 & 3) * 8;
    int r1 = aIdx1 >> 2, c1 = (aIdx1 & 3) * 8;
    int wsz0 = ((nb + r0) < N) ? 16 : 0;
    int wsz1 = ((nb + r1) < N) ? 16 : 0;

    const h16* pA0 = A   + (size_t)(mb + r0)*Kpad + c0;
    const h16* pA1 = A   + (size_t)(mb + r1)*Kpad + c1;
    const h16* pW0 = Whi + (size_t)(nb + r0)*Kpad + c0;
    const h16* pW1 = Whi + (size_t)(nb + r1)*Kpad + c1;
    const h16* pV0 = Wlo + (size_t)(nb + r0)*Kpad + c0;
    const h16* pV1 = Wlo + (size_t)(nb + r1)*Kpad + c1;

    uint32_t sbase = (uint32_t)__cvta_generic_to_shared(sm);
    auto soff = [&](int stage, int arr, int row, int col) -> uint32_t {
        return (uint32_t)((((stage*3 + arr)*128) + row)*SROW + col);
    };
    uint32_t dA0 = soff(0,0,r0,c0), dA1 = soff(0,0,r1,c1);
    uint32_t dW0 = soff(0,1,r0,c0), dW1 = soff(0,1,r1,c1);
    uint32_t dV0 = soff(0,2,r0,c0), dV1 = soff(0,2,r1,c1);
    const uint32_t STG = 3*128*SROW;

    wmma::fragment<wmma::accumulator,16,16,16,float> acc[4][2];
#pragma unroll
    for (int i = 0; i < 4; i++)
#pragma unroll
        for (int j = 0; j < 2; j++) wmma::fill_fragment(acc[i][j], 0.f);

    int ktiles = Kpad >> 5;

    cp16(sbase + 2*dA0, pA0, 16); cp16(sbase + 2*dA1, pA1, 16);
    cp16(sbase + 2*dW0, pW0, wsz0); cp16(sbase + 2*dW1, pW1, wsz1);
    cp16(sbase + 2*dV0, pV0, wsz0); cp16(sbase + 2*dV1, pV1, wsz1);
    cp_commit();

    for (int kt = 0; kt < ktiles; kt++) {
        if (kt + 1 < ktiles) {
            int st = (kt+1) & 1;
            int go = (kt+1) * 32;
            uint32_t so = st * STG;
            cp16(sbase + 2*(dA0+so), pA0 + go, 16); cp16(sbase + 2*(dA1+so), pA1 + go, 16);
            cp16(sbase + 2*(dW0+so), pW0 + go, wsz0); cp16(sbase + 2*(dW1+so), pW1 + go, wsz1);
            cp16(sbase + 2*(dV0+so), pV0 + go, wsz0); cp16(sbase + 2*(dV1+so), pV1 + go, wsz1);
            cp_commit();
            cp_wait<1>();
        } else {
            cp_wait<0>();
        }
        __syncthreads();

        if (wnvalid) {
            const h16* bA   = sm + (size_t)(kt&1)*STG + 0*128*SROW;
            const h16* bWhi = sm + (size_t)(kt&1)*STG + 1*128*SROW;
            const h16* bWlo = sm + (size_t)(kt&1)*STG + 2*128*SROW;
#pragma unroll
            for (int ks = 0; ks < 32; ks += 16) {
                wmma::fragment<wmma::matrix_b,16,16,16,h16,wmma::col_major> bhi[2], blo[2];
#pragma unroll
                for (int j = 0; j < 2; j++) {
                    wmma::load_matrix_sync(bhi[j], bWhi + (wn*32 + j*16)*SROW + ks, SROW);
                    wmma::load_matrix_sync(blo[j], bWlo + (wn*32 + j*16)*SROW + ks, SROW);
                }
#pragma unroll
                for (int i = 0; i < 4; i++) {
                    wmma::fragment<wmma::matrix_a,16,16,16,h16,wmma::row_major> af;
                    wmma::load_matrix_sync(af, bA + (wm*64 + i*16)*SROW + ks, SROW);
#pragma unroll
                    for (int j = 0; j < 2; j++) {
                        wmma::mma_sync(acc[i][j], af, bhi[j], acc[i][j]);
                        wmma::mma_sync(acc[i][j], af, blo[j], acc[i][j]);
                    }
                }
            }
        }
        __syncthreads();
    }
    if (wnvalid) {
#pragma unroll
        for (int i = 0; i < 4; i++)
#pragma unroll
            for (int j = 0; j < 2; j++) {
                int n0 = nb + wn*32 + j*16;
                if (n0 < N)
                    wmma::store_matrix_sync(C + (size_t)(mb + wm*64 + i*16)*N + n0,
                                            acc[i][j], N, wmma::mem_row_major);
            }
    }
}
#define GEMM_SMEM (2*3*128*SROW*2)   // 61440 bytes

// ---------------- megaLayer: conv + x_proj + scan1 | bar | scan2 | bar | scan3 ----------------
#define MG_AHI  0
#define MG_ALO  (CHUNK*XKS*2)
#define MG_WH   (2*CHUNK*XKS*2)
#define MG_WL   (MG_WH + 64*72*2)
#define MG_DBL  (MG_WL + 64*72*2)
#define MG_SMEM (MG_DBL + CHUNK*68*4)
__global__ void __launch_bounds__(DINNER) megaLayer(
    const float* __restrict__ conv_w, const float* __restrict__ conv_b,
    const float* __restrict__ dt_w, const float* __restrict__ dt_b,
    const float* __restrict__ D_param, int layer)
{
    extern __shared__ __align__(16) char smx[];
    h16*  Ahi  = (h16*)(smx + MG_AHI);
    h16*  Alo  = (h16*)(smx + MG_ALO);
    h16*  Wh   = (h16*)(smx + MG_WH);
    h16*  Wl   = (h16*)(smx + MG_WL);
    float* sdbl = (float*)(smx + MG_DBL);

    int c = blockIdx.x, b = blockIdx.y;
    int tid = threadIdx.x;
    int d = tid;
    int warp = tid >> 5;
    int t0 = c*CHUNK;
    int m0 = b*TSEQ + t0;

    // ---- conv phase ----
    {
        const float* wp = conv_w + (size_t)(layer*DINNER + d)*DCONV;
        float w0 = wp[0], w1 = wp[1], w2 = wp[2], w3 = wp[3];
        float bias = conv_b[layer*DINNER + d];
        size_t base = (size_t)(b*TSEQ)*(2*DINNER) + d;
        float x0 = (t0-3 >= 0) ? g_xz[base + (size_t)(t0-3)*(2*DINNER)] : 0.f;
        float x1 = (t0-2 >= 0) ? g_xz[base + (size_t)(t0-2)*(2*DINNER)] : 0.f;
        float x2 = (t0-1 >= 0) ? g_xz[base + (size_t)(t0-1)*(2*DINNER)] : 0.f;
        for (int i0 = 0; i0 < CHUNK; i0 += 8) {
            float xv[8];
#pragma unroll
            for (int j = 0; j < 8; j++)
                xv[j] = g_xz[base + (size_t)(t0+i0+j)*(2*DINNER)];
#pragma unroll
            for (int j = 0; j < 8; j++) {
                float x3 = xv[j];
                float s = bias;
                s = fmaf(w0, x0, s); s = fmaf(w1, x1, s);
                s = fmaf(w2, x2, s); s = fmaf(w3, x3, s);
                float sl = silu_f(s);
                h16 hi, lo; split_h16(sl, hi, lo);
                Ahi[(i0+j)*XKS + d] = hi;
                Alo[(i0+j)*XKS + d] = lo;
                x0 = x1; x1 = x2; x2 = x3;
            }
        }
        if (d < XK - DINNER) {
            h16 z0 = __float2half(0.f);
            for (int i = 0; i < CHUNK; i++) {
                Ahi[i*XKS + DINNER + d] = z0;
                Alo[i*XKS + DINNER + d] = z0;
            }
        }
    }
    __syncthreads();

    // ---- x_proj GEMM: sdbl[64][64] = A[64][576] @ Wx[64][576]^T (3-term) ----
    {
        wmma::fragment<wmma::accumulator,16,16,16,float> accf;
        if (warp < 16) wmma::fill_fragment(accf, 0.f);
        int ti = warp >> 2, tj = warp & 3;
        const h16* gwh = g_wx_hi + (size_t)layer*64*XK;
        const h16* gwl = g_wx_lo + (size_t)layer*64*XK;
        for (int kc = 0; kc < XK/64; kc++) {
            __syncthreads();
            for (int idx = tid; idx < 512; idx += DINNER) {
                int r = idx >> 3, q = (idx & 7)*8;
                *(uint4*)&Wh[r*72 + q] = *(const uint4*)&gwh[(size_t)r*XK + kc*64 + q];
                *(uint4*)&Wl[r*72 + q] = *(const uint4*)&gwl[(size_t)r*XK + kc*64 + q];
            }
            __syncthreads();
            if (warp < 16) {
#pragma unroll
                for (int ks = 0; ks < 64; ks += 16) {
                    wmma::fragment<wmma::matrix_a,16,16,16,h16,wmma::row_major> ah, al;
                    wmma::fragment<wmma::matrix_b,16,16,16,h16,wmma::col_major> bh, bl;
                    wmma::load_matrix_sync(ah, Ahi + ti*16*XKS + kc*64 + ks, XKS);
                    wmma::load_matrix_sync(al, Alo + ti*16*XKS + kc*64 + ks, XKS);
                    wmma::load_matrix_sync(bh, Wh + tj*16*72 + ks, 72);
                    wmma::load_matrix_sync(bl, Wl + tj*16*72 + ks, 72);
                    wmma::mma_sync(accf, ah, bh, accf);
                    wmma::mma_sync(accf, ah, bl, accf);
                    wmma::mma_sync(accf, al, bh, accf);
                }
            }
        }
        __syncthreads();
        if (warp < 16)
            wmma::store_matrix_sync(sdbl + ti*16*68 + tj*16, accf, 68, wmma::mem_row_major);
    }
    __syncthreads();

    // thread-persistent scan parameters (used by scan1 AND scan3)
    float wreg[DTRANK];
#pragma unroll
    for (int r = 0; r < DTRANK; r++)
        wreg[r] = dt_w[(size_t)(layer*DINNER + d)*DTRANK + r];
    float dbias = dt_b[layer*DINNER + d];
    float A2[DSTATE];
#pragma unroll
    for (int n = 0; n < DSTATE; n++)
        A2[n] = g_A2[(size_t)(layer*DINNER + d)*DSTATE + n];
    float ab = A2[0];
    bool fast = true;
#pragma unroll
    for (int n = 1; n < DSTATE; n++)
        fast = fast && (fabsf(A2[n] - (float)(n+1)*ab)
                        <= 1e-4f*fabsf((float)(n+1)*ab) + 1e-6f);

    // ---- scan1 phase ----
    {
        float h[DSTATE];
#pragma unroll
        for (int n = 0; n < DSTATE; n++) h[n] = 0.f;
        float sumd = 0.f;

        for (int i = 0; i < CHUNK; i++) {
            float sdt = dbias;
#pragma unroll
            for (int r = 0; r < DTRANK; r++) sdt = fmaf(sdbl[i*68 + r], wreg[r], sdt);
            float delta = softplus_f(sdt);
            float u = __half2float(Ahi[i*XKS + d]) + __half2float(Alo[i*XKS + d]);
            float du = delta * u;
            if (fast) {
                float e1 = ex2(delta * ab);
                float p = e1;
#pragma unroll
                for (int n = 0; n < DSTATE; n++) {
                    h[n] = fmaf(p, h[n], du * sdbl[i*68 + DTRANK + n]);
                    p *= e1;
                }
            } else {
#pragma unroll
                for (int n = 0; n < DSTATE; n++) {
                    float a = ex2(delta * A2[n]);
                    h[n] = fmaf(a, h[n], du * sdbl[i*68 + DTRANK + n]);
                }
            }
            sumd += delta;
        }
        size_t o = ((size_t)(b*NCHUNK + c)*DINNER + d)*DSTATE;
#pragma unroll
        for (int n = 0; n < DSTATE; n++) {
            g_hend[o + n] = h[n];
            g_P[o + n] = ex2(A2[n] * sumd);
        }
    }

    gridbar();

    // ---- scan2 phase: 1088 warp-tasks across the grid ----
    {
        int gwid = (b*NCHUNK + c)*(DINNER/32) + warp;    // 0..2175
        int lane = tid & 31;
        if (gwid < BATCH*(DINNER/2)) {
            int bb = gwid / (DINNER/2);
            int dp = gwid - bb*(DINNER/2);
            float H = 0.f;
            for (int cc = 0; cc < NCHUNK; cc++) {
                size_t o = ((size_t)(bb*NCHUNK + cc)*DINNER + dp*2)*DSTATE + lane;
                float P = g_P[o];
                float E = g_hend[o];
                g_Hin[o] = H;
                H = fmaf(P, H, E);
            }
        }
    }

    gridbar();

    // ---- scan3 phase: reuse smem sdbl + Ahi/Alo (u), registers wreg/A2 ----
    {
        size_t base = (size_t)(b*TSEQ)*(2*DINNER) + d;
        float h[DSTATE];
        size_t oin = ((size_t)(b*NCHUNK + c)*DINNER + d)*DSTATE;
#pragma unroll
        for (int n = 0; n < DSTATE; n++) h[n] = g_Hin[oin + n];
        float Dp = D_param[layer*DINNER + d];

        for (int i0 = 0; i0 < CHUNK; i0 += 8) {
            float zv[8];
#pragma unroll
            for (int j = 0; j < 8; j++)
                zv[j] = g_xz[base + (size_t)(t0+i0+j)*(2*DINNER) + DINNER];
#pragma unroll
            for (int j = 0; j < 8; j++) {
                int i = i0 + j;
                int m = m0 + i;
                float u = __half2float(Ahi[i*XKS + d]) + __half2float(Alo[i*XKS + d]);

                float sdt = dbias;
#pragma unroll
                for (int r = 0; r < DTRANK; r++) sdt = fmaf(sdbl[i*68 + r], wreg[r], sdt);
                float delta = softplus_f(sdt);
                float du = delta * u;
                float y = 0.f;
                if (fast) {
                    float e1 = ex2(delta * ab);
                    float p = e1;
#pragma unroll
                    for (int n = 0; n < DSTATE; n++) {
                        h[n] = fmaf(p, h[n], du * sdbl[i*68 + DTRANK + n]);
                        y = fmaf(h[n], sdbl[i*68 + DTRANK + DSTATE + n], y);
                        p *= e1;
                    }
                } else {
#pragma unroll
                    for (int n = 0; n < DSTATE; n++) {
                        float a = ex2(delta * A2[n]);
                        h[n] = fmaf(a, h[n], du * sdbl[i*68 + DTRANK + n]);
                        y = fmaf(h[n], sdbl[i*68 + DTRANK + DSTATE + n], y);
                    }
                }
                float silz = silu_f(zv[j]);
                float yg = fmaf(u, Dp, y) * silz;
                g_yg[(size_t)m*DINNER + d] = __float2half_rn(yg);
            }
        }
    }
}

// ---------------- host launcher ----------------
extern "C" void kernel_launch(void* const* d_in, const int* in_sizes, int n_in,
                              void* d_out, int out_size)
{
    (void)in_sizes; (void)n_in; (void)out_size;
    const int*   type_seq = (const int*)  d_in[0];
    const float* time_seq = (const float*)d_in[1];
    const float* temp_seq = (const float*)d_in[2];
    const float* emb      = (const float*)d_in[3];
    const float* norm_w   = (const float*)d_in[4];
    const float* norm_b   = (const float*)d_in[5];
    const float* in_w     = (const float*)d_in[6];
    const float* conv_w   = (const float*)d_in[7];
    const float* conv_b   = (const float*)d_in[8];
    const float* xproj_w  = (const float*)d_in[9];
    const float* dt_w     = (const float*)d_in[10];
    const float* dt_b     = (const float*)d_in[11];
    const float* A_log    = (const float*)d_in[12];
    const float* D_param  = (const float*)d_in[13];
    const float* out_w    = (const float*)d_in[14];
    const float* normf_w  = (const float*)d_in[15];
    const float* normf_b  = (const float*)d_in[16];
    float* out = (float*)d_out;

    float *p_xz, *p_h;
    cudaGetSymbolAddress((void**)&p_xz, g_xz);
    cudaGetSymbolAddress((void**)&p_h,  g_h);
    h16 *p_hn, *p_yg, *p_w1h, *p_w1l, *p_w2h, *p_w2l;
    cudaGetSymbolAddress((void**)&p_hn,  g_hn);
    cudaGetSymbolAddress((void**)&p_yg,  g_yg);
    cudaGetSymbolAddress((void**)&p_w1h, g_w1_hi);
    cudaGetSymbolAddress((void**)&p_w1l, g_w1_lo);
    cudaGetSymbolAddress((void**)&p_w2h, g_w2_hi);
    cudaGetSymbolAddress((void**)&p_w2l, g_w2_lo);

    cudaFuncSetAttribute(gemm_h16,
                         cudaFuncAttributeMaxDynamicSharedMemorySize, GEMM_SMEM);
    cudaFuncSetAttribute(megaLayer,
                         cudaFuncAttributeMaxDynamicSharedMemorySize, MG_SMEM);

    embed_kernel<<<MROWS, DDIM>>>(type_seq, time_seq, temp_seq, emb);
    prep_all<<<(W1TOT + W2TOT + WXTOT + A2TOT + 255)/256, 256>>>(
        in_w, out_w, xproj_w, A_log);

    for (int l = 0; l < NLAYER; l++) {
        addnorm_kernel<<<MROWS/8, 256>>>(norm_w + l*DDIM, norm_b + l*DDIM, l > 0);

        gemm_h16<<<dim3((2*DINNER + 127)/128, MROWS/128), 256, GEMM_SMEM>>>(
            p_hn,
            p_w1h + (size_t)l*2*DINNER*KPAD1, p_w1l + (size_t)l*2*DINNER*KPAD1,
            p_xz, MROWS, 2*DINNER, KPAD1);

        megaLayer<<<dim3(NCHUNK, BATCH), DINNER, MG_SMEM>>>(
            conv_w, conv_b, dt_w, dt_b, D_param, l);

        gemm_h16<<<dim3((DDIM + 127)/128, MROWS/128), 256, GEMM_SMEM>>>(
            p_yg,
            p_w2h + (size_t)l*DDIM*DINNER, p_w2l + (size_t)l*DDIM*DINNER,
            p_h, MROWS, DDIM, DINNER);
    }

    final_kernel<<<(BATCH*LQ)/8, 256>>>(normf_w, normf_b, out);
}